// round 8
// baseline (speedup 1.0000x reference)
#include <cuda_runtime.h>
#include <cuda_bf16.h>
#include <stdint.h>
#include <math.h>

#define B_SZ 8192
#define F    40
#define E    8
#define FE   320
#define RDIM 5
#define P    780
#define K1   12480
#define N1   1024
#define N2   512

// ---- GEMM tiling ----
#define BM 128
#define BN 128
#define BK 32
#define TILE_B 8192                      // 128 rows x 64B (swizzled, no padding)
#define STAGE_B (4 * TILE_B)             // Ah, Al, Bh, Bl = 32KB
#define NSTAGE 3
#define GEMM_SMEM (NSTAGE * STAGE_B)     // 98304 -> 2 CTAs/SM

// ---- stream-K for GEMM1 ----
#define NKT1  (K1 / BK)                  // 390 kt per tile
#define NTM1  (B_SZ / BM)                // 64
#define NTN1  (N1 / BN)                  // 8
#define NT1   (NTM1 * NTN1)              // 512 tiles
#define NCTA1 296                        // 148 SMs x 2 CTAs
#define U1    ((size_t)NT1 * NKT1)       // 199680 work units

// -------------------- device scratch --------------------
__device__ __nv_bfloat16 g_h_hi [(size_t)B_SZ * K1];
__device__ __nv_bfloat16 g_h_lo [(size_t)B_SZ * K1];
__device__ __nv_bfloat16 g_w1_hi[(size_t)N1 * K1];
__device__ __nv_bfloat16 g_w1_lo[(size_t)N1 * K1];
__device__ __nv_bfloat16 g_y1_hi[(size_t)B_SZ * N1];
__device__ __nv_bfloat16 g_y1_lo[(size_t)B_SZ * N1];
__device__ __nv_bfloat16 g_w2_hi[(size_t)N2 * N1];
__device__ __nv_bfloat16 g_w2_lo[(size_t)N2 * N1];
__device__ float         g_y2  [(size_t)B_SZ * N2];
__device__ float         g_p0  [(size_t)NT1 * BM * BN];   // stream-K partial (k-head)
__device__ float         g_p1  [(size_t)NT1 * BM * BN];   // stream-K partial (k-tail)

// -------------------- helpers --------------------
__device__ __forceinline__ uint32_t smem_u32(const void* p) {
    uint32_t a;
    asm("{ .reg .u64 t; cvta.to.shared.u64 t, %1; cvt.u32.u64 %0, t; }" : "=r"(a) : "l"(p));
    return a;
}
__device__ __forceinline__ void cp16(uint32_t dst, const void* src) {
    asm volatile("cp.async.cg.shared.global [%0], [%1], 16;" :: "r"(dst), "l"(src));
}
__device__ __forceinline__ void ldsm_x4(uint32_t* r, uint32_t addr) {
    asm volatile("ldmatrix.sync.aligned.m8n8.x4.shared.b16 {%0,%1,%2,%3}, [%4];"
                 : "=r"(r[0]), "=r"(r[1]), "=r"(r[2]), "=r"(r[3]) : "r"(addr));
}
__device__ __forceinline__ void mma_bf16(float* c, const uint32_t* a, const uint32_t* b) {
    asm volatile(
        "mma.sync.aligned.m16n8k16.row.col.f32.bf16.bf16.f32 "
        "{%0,%1,%2,%3}, {%4,%5,%6,%7}, {%8,%9}, {%0,%1,%2,%3};"
        : "+f"(c[0]), "+f"(c[1]), "+f"(c[2]), "+f"(c[3])
        : "r"(a[0]), "r"(a[1]), "r"(a[2]), "r"(a[3]), "r"(b[0]), "r"(b[1]));
}
// swizzled byte offset within an 8KB tile: row r (0..127), byte col bc (0..63, 16B-aligned)
__device__ __forceinline__ uint32_t swz(int r, int bc) {
    return (uint32_t)(r * 64 + ((((bc) >> 4) ^ ((r >> 1) & 3)) << 4));
}

// ---------------------------------------------------------------------------
// Kernel A: BN + SENet + bilinear -> h (bf16 hi/lo split)
// ---------------------------------------------------------------------------
__global__ __launch_bounds__(256) void feat_kernel(
    const float* __restrict__ emb,  const float* __restrict__ bn_w,
    const float* __restrict__ bn_b, const float* __restrict__ bn_m,
    const float* __restrict__ bn_v, const float* __restrict__ se_w1,
    const float* __restrict__ se_w2,const float* __restrict__ w_bl,
    __nv_bfloat16* __restrict__ h_hi, __nv_bfloat16* __restrict__ h_lo)
{
    __shared__ float sV[FE], sT[FE], sZ[F], sH[RDIM], sA[F], sW[E*E];
    __shared__ unsigned char s_pi[P], s_pj[P];

    const int tid = threadIdx.x;
    const int b   = blockIdx.x;

    if (tid == 0) {
        int p = 0;
        for (int i = 0; i < F; i++)
            for (int j = i + 1; j < F; j++) { s_pi[p] = (unsigned char)i; s_pj[p] = (unsigned char)j; p++; }
    }
    if (tid < E*E) sW[tid] = w_bl[tid];

    for (int idx = tid; idx < FE; idx += 256) {
        float x   = emb[(size_t)b * FE + idx];
        float inv = rsqrtf(bn_v[idx] + 1e-5f);
        sV[idx]   = (x - bn_m[idx]) * inv * bn_w[idx] + bn_b[idx];
    }
    __syncthreads();

    if (tid < F) {
        float s = 0.f;
        #pragma unroll
        for (int e = 0; e < E; e++) s += sV[tid * E + e];
        sZ[tid] = s * (1.f / E);
    }
    __syncthreads();

    if (tid < RDIM) {
        float s = 0.f;
        #pragma unroll
        for (int f = 0; f < F; f++) s += sZ[f] * se_w1[tid * F + f];
        sH[tid] = fmaxf(s, 0.f);
    }
    __syncthreads();

    if (tid < F) {
        float s = 0.f;
        #pragma unroll
        for (int r = 0; r < RDIM; r++) s += sH[r] * se_w2[tid * RDIM + r];
        sA[tid] = fmaxf(s, 0.f);
    }

    for (int idx = tid; idx < FE; idx += 256) {
        int f = idx >> 3, d = idx & 7;
        float s = 0.f;
        #pragma unroll
        for (int e = 0; e < E; e++) s += sV[f * E + e] * sW[d * E + e];
        sT[idx] = s;
    }
    __syncthreads();

    __nv_bfloat16* ohi = h_hi + (size_t)b * K1;
    __nv_bfloat16* olo = h_lo + (size_t)b * K1;
    for (int idx = tid; idx < K1; idx += 256) {
        int q = (idx < P * E) ? idx : (idx - P * E);
        int p = q >> 3, d = q & 7;
        int i = s_pi[p], j = s_pj[p];
        float v = sT[i * E + d] * sV[j * E + d];
        if (idx < P * E) v *= sA[i] * sA[j];
        __nv_bfloat16 hh = __float2bfloat16(v);
        ohi[idx] = hh;
        olo[idx] = __float2bfloat16(v - __bfloat162float(hh));
    }
}

// ---------------------------------------------------------------------------
// Weight split fp32 -> bf16 hi/lo
// ---------------------------------------------------------------------------
__global__ __launch_bounds__(256) void split_kernel(
    const float* __restrict__ src, __nv_bfloat16* __restrict__ hi,
    __nv_bfloat16* __restrict__ lo, size_t n)
{
    for (size_t i = (size_t)blockIdx.x * blockDim.x + threadIdx.x; i < n;
         i += (size_t)gridDim.x * blockDim.x) {
        float v = src[i];
        __nv_bfloat16 h = __float2bfloat16(v);
        hi[i] = h;
        lo[i] = __float2bfloat16(v - __bfloat162float(h));
    }
}

// ---------------------------------------------------------------------------
// GEMM1 stream-K phase 1: 296 persistent CTAs, equal kt-unit ranges.
// Whole tiles -> direct bf16 hi/lo epilogue. Split tiles -> fp32 partials.
// ---------------------------------------------------------------------------
__global__ void __launch_bounds__(256, 2) gemm1_sk(
    const __nv_bfloat16* __restrict__ Ahi, const __nv_bfloat16* __restrict__ Alo,
    const __nv_bfloat16* __restrict__ Bhi, const __nv_bfloat16* __restrict__ Blo,
    const float* __restrict__ bias,
    __nv_bfloat16* __restrict__ Ohi, __nv_bfloat16* __restrict__ Olo,
    float* __restrict__ p0, float* __restrict__ p1)
{
    extern __shared__ char smem[];
    const uint32_t sb  = smem_u32(smem);
    const int tid  = threadIdx.x;
    const int warp = tid >> 5, lane = tid & 31;
    const int wm   = warp & 3;
    const int wn   = warp >> 2;

    // per-thread load coords
    const int r0 = tid >> 2, c0 = tid & 3;
    const uint32_t s_off0 = swz(r0, c0 * 16);
    const uint32_t s_off1 = swz(r0 + 64, c0 * 16);
    const size_t rowK  = (size_t)K1 * 2;
    const size_t g_off0 = (size_t)r0 * rowK + c0 * 16;
    const size_t g_off1 = (size_t)(r0 + 64) * rowK + c0 * 16;

    // ldmatrix lane coords (tile-local)
    const int a_row = wm * 32 + (lane & 15);
    const int a_col = (lane >> 4) * 8;
    const int b_row = wn * 64 + ((lane >> 4) << 3) + (lane & 7);
    const int b_col = ((lane >> 3) & 1) * 8;

    size_t beg = (size_t)blockIdx.x       * U1 / NCTA1;
    size_t end = (size_t)(blockIdx.x + 1) * U1 / NCTA1;

    while (beg < end) {
        const int t  = (int)(beg / NKT1);
        const int k0 = (int)(beg % NKT1);
        int L = NKT1 - k0;
        if ((size_t)L > end - beg) L = (int)(end - beg);
        const int bm = t >> 3, bn = t & 7;

        const char* pAh = (const char*)(Ahi + (size_t)bm * BM * K1);
        const char* pAl = (const char*)(Alo + (size_t)bm * BM * K1);
        const char* pBh = (const char*)(Bhi + (size_t)bn * BN * K1);
        const char* pBl = (const char*)(Blo + (size_t)bn * BN * K1);

        float acc[2][8][4];
        #pragma unroll
        for (int i = 0; i < 2; i++)
            #pragma unroll
            for (int j = 0; j < 8; j++)
                #pragma unroll
                for (int r = 0; r < 4; r++) acc[i][j][r] = 0.f;

        auto load_stage = [&](int s, int kt) {
            const uint32_t base = sb + s * STAGE_B;
            const size_t koff = (size_t)kt * (BK * 2);
            cp16(base + s_off0,              pAh + g_off0 + koff);
            cp16(base + s_off1,              pAh + g_off1 + koff);
            cp16(base + TILE_B + s_off0,     pAl + g_off0 + koff);
            cp16(base + TILE_B + s_off1,     pAl + g_off1 + koff);
            cp16(base + 2 * TILE_B + s_off0, pBh + g_off0 + koff);
            cp16(base + 2 * TILE_B + s_off1, pBh + g_off1 + koff);
            cp16(base + 3 * TILE_B + s_off0, pBl + g_off0 + koff);
            cp16(base + 3 * TILE_B + s_off1, pBl + g_off1 + koff);
        };

        load_stage(0, k0);
        asm volatile("cp.async.commit_group;" ::: "memory");
        if (L > 1) load_stage(1, k0 + 1);
        asm volatile("cp.async.commit_group;" ::: "memory");

        for (int i = 0; i < L; i++) {
            const int s = i % NSTAGE;
            asm volatile("cp.async.wait_group 1;" ::: "memory");
            __syncthreads();

            const uint32_t base   = sb + s * STAGE_B;
            const uint32_t baseAh = base;
            const uint32_t baseAl = base + TILE_B;
            const uint32_t baseBh = base + 2 * TILE_B;
            const uint32_t baseBl = base + 3 * TILE_B;

            #pragma unroll
            for (int ks = 0; ks < 2; ks++) {
                const int k16 = ks * 16;
                uint32_t ah[2][4], al[2][4];
                #pragma unroll
                for (int mt = 0; mt < 2; mt++) {
                    uint32_t off = swz(a_row + mt * 16, (k16 + a_col) * 2);
                    ldsm_x4(ah[mt], baseAh + off);
                    ldsm_x4(al[mt], baseAl + off);
                }
                #pragma unroll
                for (int half = 0; half < 2; half++) {
                    uint32_t bh[4][2], bl[4][2];
                    #pragma unroll
                    for (int np = 0; np < 2; np++) {
                        uint32_t off = swz(b_row + (half * 2 + np) * 16, (k16 + b_col) * 2);
                        uint32_t rh[4], rl[4];
                        ldsm_x4(rh, baseBh + off);
                        ldsm_x4(rl, baseBl + off);
                        bh[np*2][0]   = rh[0]; bh[np*2][1]   = rh[1];
                        bh[np*2+1][0] = rh[2]; bh[np*2+1][1] = rh[3];
                        bl[np*2][0]   = rl[0]; bl[np*2][1]   = rl[1];
                        bl[np*2+1][0] = rl[2]; bl[np*2+1][1] = rl[3];
                    }
                    #pragma unroll
                    for (int mt = 0; mt < 2; mt++)
                        #pragma unroll
                        for (int nt = 0; nt < 4; nt++) {
                            float* a4 = acc[mt][half * 4 + nt];
                            mma_bf16(a4, ah[mt], bh[nt]);
                            mma_bf16(a4, ah[mt], bl[nt]);
                            mma_bf16(a4, al[mt], bh[nt]);
                        }
                }
            }

            __syncthreads();
            if (i + 2 < L) load_stage((i + 2) % NSTAGE, k0 + i + 2);
            asm volatile("cp.async.commit_group;" ::: "memory");
        }
        asm volatile("cp.async.wait_group 0;" ::: "memory");

        // ---- epilogue for this segment ----
        const bool full = (k0 == 0) && (L == NKT1);
        const int ml0 = wm * 32 + (lane >> 2);
        const int nl0 = wn * 64 + (lane & 3) * 2;
        if (full) {
            #pragma unroll
            for (int mt = 0; mt < 2; mt++)
                #pragma unroll
                for (int half = 0; half < 2; half++) {
                    const int m = bm * BM + ml0 + mt * 16 + half * 8;
                    #pragma unroll
                    for (int nt = 0; nt < 8; nt++) {
                        const int n = bn * BN + nl0 + nt * 8;
                        float v0 = fmaxf(acc[mt][nt][half*2+0] + __ldg(&bias[n]),   0.f);
                        float v1 = fmaxf(acc[mt][nt][half*2+1] + __ldg(&bias[n+1]), 0.f);
                        __nv_bfloat16 h0 = __float2bfloat16(v0);
                        __nv_bfloat16 h1 = __float2bfloat16(v1);
                        __nv_bfloat162 hv; hv.x = h0; hv.y = h1;
                        __nv_bfloat162 lv;
                        lv.x = __float2bfloat16(v0 - __bfloat162float(h0));
                        lv.y = __float2bfloat16(v1 - __bfloat162float(h1));
                        *(__nv_bfloat162*)(Ohi + (size_t)m * N1 + n) = hv;
                        *(__nv_bfloat162*)(Olo + (size_t)m * N1 + n) = lv;
                    }
                }
        } else {
            float* pp = ((k0 == 0) ? p0 : p1) + (size_t)t * (BM * BN);
            #pragma unroll
            for (int mt = 0; mt < 2; mt++)
                #pragma unroll
                for (int half = 0; half < 2; half++) {
                    const int ml = ml0 + mt * 16 + half * 8;
                    #pragma unroll
                    for (int nt = 0; nt < 8; nt++) {
                        const int nl = nl0 + nt * 8;
                        float2 fv;
                        fv.x = acc[mt][nt][half*2+0];
                        fv.y = acc[mt][nt][half*2+1];
                        *(float2*)(pp + ml * BN + nl) = fv;
                    }
                }
        }
        beg += L;
    }
}

// ---------------------------------------------------------------------------
// GEMM1 stream-K phase 2: combine partials for split tiles (deterministic,
// split-set recomputed arithmetically — no flags).
// ---------------------------------------------------------------------------
__global__ __launch_bounds__(256) void gemm1_fix(
    const float* __restrict__ p0, const float* __restrict__ p1,
    const float* __restrict__ bias,
    __nv_bfloat16* __restrict__ Ohi, __nv_bfloat16* __restrict__ Olo)
{
    const int t = blockIdx.x;
    const unsigned long long lo = (unsigned long long)t * NKT1;
    // smallest CTA boundary strictly greater than lo
    unsigned long long c = ((lo + 1) * NCTA1 + U1 - 1) / U1;
    if (c < 1 || c > NCTA1 - 1) return;
    unsigned long long bnd = c * U1 / NCTA1;
    if (bnd >= lo + NKT1) return;   // no interior boundary -> tile was whole

    const int bm = t >> 3, bn = t & 7;
    const float* a = p0 + (size_t)t * (BM * BN);
    const float* b = p1 + (size_t)t * (BM * BN);

    #pragma unroll 4
    for (int j = 0; j < (BM * BN) / 256; j++) {
        const int idx = threadIdx.x + j * 256;
        const int ml = idx >> 7, nl = idx & 127;
        const int n = bn * BN + nl;
        float v = fmaxf(a[idx] + b[idx] + bias[n], 0.f);
        __nv_bfloat16 h = __float2bfloat16(v);
        const size_t o = (size_t)(bm * BM + ml) * N1 + n;
        Ohi[o] = h;
        Olo[o] = __float2bfloat16(v - __bfloat162float(h));
    }
}

// ---------------------------------------------------------------------------
// bf16x3 GEMM (NT) via mma.sync — classic tiled version (used for GEMM2).
// mode 1: write fp32.
// ---------------------------------------------------------------------------
__global__ void __launch_bounds__(256, 2) gemm_bf16x3(
    const __nv_bfloat16* __restrict__ Ahi, const __nv_bfloat16* __restrict__ Alo,
    const __nv_bfloat16* __restrict__ Bhi, const __nv_bfloat16* __restrict__ Blo,
    const float* __restrict__ bias,
    float* __restrict__ Of,
    int Nfull, int K)
{
    extern __shared__ char smem[];
    const uint32_t sb  = smem_u32(smem);
    const int tid  = threadIdx.x;
    const int warp = tid >> 5, lane = tid & 31;
    const int wm   = warp & 3;
    const int wn   = warp >> 2;
    const int bn   = blockIdx.x, bm = blockIdx.y;
    const int nkt  = K / BK;

    const char* pAh = (const char*)(Ahi + (size_t)bm * BM * K);
    const char* pAl = (const char*)(Alo + (size_t)bm * BM * K);
    const char* pBh = (const char*)(Bhi + (size_t)bn * BN * K);
    const char* pBl = (const char*)(Blo + (size_t)bn * BN * K);
    const size_t rowK = (size_t)K * 2;

    const int r0 = tid >> 2, c0 = tid & 3;
    const uint32_t s_off0 = swz(r0, c0 * 16);
    const uint32_t s_off1 = swz(r0 + 64, c0 * 16);
    const size_t  g_off0 = (size_t)r0 * rowK + c0 * 16;
    const size_t  g_off1 = (size_t)(r0 + 64) * rowK + c0 * 16;

    auto load_stage = [&](int s, int kt) {
        const uint32_t base = sb + s * STAGE_B;
        const size_t koff = (size_t)kt * (BK * 2);
        cp16(base + s_off0,              pAh + g_off0 + koff);
        cp16(base + s_off1,              pAh + g_off1 + koff);
        cp16(base + TILE_B + s_off0,     pAl + g_off0 + koff);
        cp16(base + TILE_B + s_off1,     pAl + g_off1 + koff);
        cp16(base + 2 * TILE_B + s_off0, pBh + g_off0 + koff);
        cp16(base + 2 * TILE_B + s_off1, pBh + g_off1 + koff);
        cp16(base + 3 * TILE_B + s_off0, pBl + g_off0 + koff);
        cp16(base + 3 * TILE_B + s_off1, pBl + g_off1 + koff);
        asm volatile("cp.async.commit_group;" ::: "memory");
    };

    float acc[2][8][4];
    #pragma unroll
    for (int i = 0; i < 2; i++)
        #pragma unroll
        for (int j = 0; j < 8; j++)
            #pragma unroll
            for (int r = 0; r < 4; r++) acc[i][j][r] = 0.f;

    load_stage(0, 0);
    if (nkt > 1) load_stage(1, 1); else asm volatile("cp.async.commit_group;" ::: "memory");

    const int a_row = wm * 32 + (lane & 15);
    const int a_col = (lane >> 4) * 8;
    const int b_row = wn * 64 + ((lane >> 4) << 3) + (lane & 7);
    const int b_col = ((lane >> 3) & 1) * 8;

    for (int kt = 0; kt < nkt; kt++) {
        const int s = kt % NSTAGE;
        asm volatile("cp.async.wait_group 1;" ::: "memory");
        __syncthreads();

        const uint32_t base   = sb + s * STAGE_B;
        const uint32_t baseAh = base;
        const uint32_t baseAl = base + TILE_B;
        const uint32_t baseBh = base + 2 * TILE_B;
        const uint32_t baseBl = base + 3 * TILE_B;

        #pragma unroll
        for (int ks = 0; ks < 2; ks++) {
            const int k0 = ks * 16;
            uint32_t ah[2][4], al[2][4];
            #pragma unroll
            for (int mt = 0; mt < 2; mt++) {
                uint32_t off = swz(a_row + mt * 16, (k0 + a_col) * 2);
                ldsm_x4(ah[mt], baseAh + off);
                ldsm_x4(al[mt], baseAl + off);
            }
            #pragma unroll
            for (int half = 0; half < 2; half++) {
                uint32_t bh[4][2], bl[4][2];
                #pragma unroll
                for (int np = 0; np < 2; np++) {
                    uint32_t off = swz(b_row + (half * 2 + np) * 16, (k0 + b_col) * 2);
                    uint32_t rh[4], rl[4];
                    ldsm_x4(rh, baseBh + off);
                    ldsm_x4(rl, baseBl + off);
                    bh[np*2][0]   = rh[0]; bh[np*2][1]   = rh[1];
                    bh[np*2+1][0] = rh[2]; bh[np*2+1][1] = rh[3];
                    bl[np*2][0]   = rl[0]; bl[np*2][1]   = rl[1];
                    bl[np*2+1][0] = rl[2]; bl[np*2+1][1] = rl[3];
                }
                #pragma unroll
                for (int mt = 0; mt < 2; mt++)
                    #pragma unroll
                    for (int nt = 0; nt < 4; nt++) {
                        float* a4 = acc[mt][half * 4 + nt];
                        mma_bf16(a4, ah[mt], bh[nt]);
                        mma_bf16(a4, ah[mt], bl[nt]);
                        mma_bf16(a4, al[mt], bh[nt]);
                    }
            }
        }

        __syncthreads();
        if (kt + 2 < nkt) load_stage((kt + 2) % NSTAGE, kt + 2);
        else asm volatile("cp.async.commit_group;" ::: "memory");
    }

    const int m_base = bm * BM + wm * 32 + (lane >> 2);
    const int n_base = bn * BN + wn * 64 + (lane & 3) * 2;
    #pragma unroll
    for (int mt = 0; mt < 2; mt++) {
        #pragma unroll
        for (int half = 0; half < 2; half++) {
            const int m = m_base + mt * 16 + half * 8;
            #pragma unroll
            for (int nt = 0; nt < 8; nt++) {
                const int n = n_base + nt * 8;
                float2 fv;
                fv.x = fmaxf(acc[mt][nt][half*2+0] + __ldg(&bias[n]),   0.f);
                fv.y = fmaxf(acc[mt][nt][half*2+1] + __ldg(&bias[n+1]), 0.f);
                *(float2*)(Of + (size_t)m * Nfull + n) = fv;
            }
        }
    }
}

// ---------------------------------------------------------------------------
// Final: out[b] = sigmoid( y2[b,:] . w3 + b3 )
// ---------------------------------------------------------------------------
__global__ __launch_bounds__(256) void final_kernel(
    const float* __restrict__ y2, const float* __restrict__ w3,
    const float* __restrict__ b3, float* __restrict__ out)
{
    __shared__ float sw[N2];
    const int tid = threadIdx.x;
    for (int i = tid; i < N2; i += 256) sw[i] = w3[i];
    __syncthreads();

    const int warp = tid >> 5, lane = tid & 31;
    const int row  = blockIdx.x * 8 + warp;
    const float* yr = y2 + (size_t)row * N2;

    float s = 0.f;
    #pragma unroll 4
    for (int k = lane; k < N2; k += 32) s = fmaf(yr[k], sw[k], s);
    #pragma unroll
    for (int o = 16; o; o >>= 1) s += __shfl_xor_sync(0xffffffffu, s, o);
    if (lane == 0) out[row] = 1.f / (1.f + expf(-(s + b3[0])));
}

// ---------------------------------------------------------------------------
extern "C" void kernel_launch(void* const* d_in, const int* in_sizes, int n_in,
                              void* d_out, int out_size)
{
    const float* emb   = (const float*)d_in[0];
    const float* bn_w  = (const float*)d_in[1];
    const float* bn_b  = (const float*)d_in[2];
    const float* bn_m  = (const float*)d_in[3];
    const float* bn_v  = (const float*)d_in[4];
    const float* se_w1 = (const float*)d_in[5];
    const float* se_w2 = (const float*)d_in[6];
    const float* w_bl  = (const float*)d_in[7];
    const float* d_w1  = (const float*)d_in[8];
    const float* d_b1  = (const float*)d_in[9];
    const float* d_w2  = (const float*)d_in[10];
    const float* d_b2  = (const float*)d_in[11];
    const float* d_w3  = (const float*)d_in[12];
    const float* d_b3  = (const float*)d_in[13];
    float* out = (float*)d_out;

    __nv_bfloat16 *h_hi, *h_lo, *w1_hi, *w1_lo, *y1_hi, *y1_lo, *w2_hi, *w2_lo;
    float *y2, *p0, *p1;
    cudaGetSymbolAddress((void**)&h_hi,  g_h_hi);
    cudaGetSymbolAddress((void**)&h_lo,  g_h_lo);
    cudaGetSymbolAddress((void**)&w1_hi, g_w1_hi);
    cudaGetSymbolAddress((void**)&w1_lo, g_w1_lo);
    cudaGetSymbolAddress((void**)&y1_hi, g_y1_hi);
    cudaGetSymbolAddress((void**)&y1_lo, g_y1_lo);
    cudaGetSymbolAddress((void**)&w2_hi, g_w2_hi);
    cudaGetSymbolAddress((void**)&w2_lo, g_w2_lo);
    cudaGetSymbolAddress((void**)&y2,    g_y2);
    cudaGetSymbolAddress((void**)&p0,    g_p0);
    cudaGetSymbolAddress((void**)&p1,    g_p1);

    cudaFuncSetAttribute(gemm1_sk,    cudaFuncAttributeMaxDynamicSharedMemorySize, GEMM_SMEM);
    cudaFuncSetAttribute(gemm_bf16x3, cudaFuncAttributeMaxDynamicSharedMemorySize, GEMM_SMEM);

    // 1) feature construction (bf16 hi/lo)
    feat_kernel<<<B_SZ, 256>>>(emb, bn_w, bn_b, bn_m, bn_v, se_w1, se_w2, w_bl, h_hi, h_lo);

    // 2) weight splits
    split_kernel<<<4096, 256>>>(d_w1, w1_hi, w1_lo, (size_t)N1 * K1);
    split_kernel<<<1024, 256>>>(d_w2, w2_hi, w2_lo, (size_t)N2 * N1);

    // 3) GEMM1 stream-K: [8192,12480] x [1024,12480]^T + relu -> y1 (bf16 split)
    gemm1_sk<<<NCTA1, 256, GEMM_SMEM>>>(h_hi, h_lo, w1_hi, w1_lo, d_b1,
                                        y1_hi, y1_lo, p0, p1);
    gemm1_fix<<<NT1, 256>>>(p0, p1, d_b1, y1_hi, y1_lo);

    // 4) GEMM2: [8192,1024] x [512,1024]^T + relu -> y2 (fp32)
    dim3 g2(N2 / BN, B_SZ / BM);
    gemm_bf16x3<<<g2, 256, GEMM_SMEM>>>(y1_hi, y1_lo, w2_hi, w2_lo, d_b2, y2, N2, N1);

    // 5) GEMV + sigmoid
    final_kernel<<<B_SZ / 8, 256>>>(y2, d_w3, d_b3, out);
}

// round 11
// speedup vs baseline: 1.0182x; 1.0182x over previous
#include <cuda_runtime.h>
#include <cuda_bf16.h>
#include <stdint.h>
#include <math.h>

#define B_SZ 8192
#define F    40
#define E    8
#define FE   320
#define RDIM 5
#define P    780
#define K1   12480
#define N1   1024
#define N2   512

// ---- GEMM tiling ----
#define BM 128
#define BN 128
#define BK 32
#define TILE_B 8192                      // 128 rows x 64B (swizzled, no padding)
#define STAGE_B (4 * TILE_B)             // Ah, Al, Bh, Bl = 32KB
#define NSTAGE 3
#define GEMM_SMEM (NSTAGE * STAGE_B)     // 98304 -> 2 CTAs/SM

// ---- stream-K for GEMM1 ----
#define NKT1  (K1 / BK)                  // 390 kt per tile
#define NTM1  (B_SZ / BM)                // 64
#define NTN1  (N1 / BN)                  // 8
#define NT1   (NTM1 * NTN1)              // 512 tiles
#define NCTA1 296                        // 148 SMs x 2 CTAs
#define U1    ((size_t)NT1 * NKT1)       // 199680 work units

// -------------------- device scratch --------------------
__device__ __nv_bfloat16 g_h_hi [(size_t)B_SZ * K1];
__device__ __nv_bfloat16 g_h_lo [(size_t)B_SZ * K1];
__device__ __nv_bfloat16 g_w1_hi[(size_t)N1 * K1];
__device__ __nv_bfloat16 g_w1_lo[(size_t)N1 * K1];
__device__ __nv_bfloat16 g_y1_hi[(size_t)B_SZ * N1];
__device__ __nv_bfloat16 g_y1_lo[(size_t)B_SZ * N1];
__device__ __nv_bfloat16 g_w2_hi[(size_t)N2 * N1];
__device__ __nv_bfloat16 g_w2_lo[(size_t)N2 * N1];
__device__ float         g_y2  [(size_t)B_SZ * N2];
__device__ float         g_p0  [(size_t)NT1 * BM * BN];   // stream-K partial (k-head)
__device__ float         g_p1  [(size_t)NT1 * BM * BN];   // stream-K partial (k-tail)

// -------------------- helpers --------------------
__device__ __forceinline__ uint32_t smem_u32(const void* p) {
    uint32_t a;
    asm("{ .reg .u64 t; cvta.to.shared.u64 t, %1; cvt.u32.u64 %0, t; }" : "=r"(a) : "l"(p));
    return a;
}
__device__ __forceinline__ void cp16(uint32_t dst, const void* src) {
    asm volatile("cp.async.cg.shared.global [%0], [%1], 16;" :: "r"(dst), "l"(src));
}
__device__ __forceinline__ void ldsm_x4(uint32_t* r, uint32_t addr) {
    asm volatile("ldmatrix.sync.aligned.m8n8.x4.shared.b16 {%0,%1,%2,%3}, [%4];"
                 : "=r"(r[0]), "=r"(r[1]), "=r"(r[2]), "=r"(r[3]) : "r"(addr));
}
__device__ __forceinline__ void mma_bf16(float* c, const uint32_t* a, const uint32_t* b) {
    asm volatile(
        "mma.sync.aligned.m16n8k16.row.col.f32.bf16.bf16.f32 "
        "{%0,%1,%2,%3}, {%4,%5,%6,%7}, {%8,%9}, {%0,%1,%2,%3};"
        : "+f"(c[0]), "+f"(c[1]), "+f"(c[2]), "+f"(c[3])
        : "r"(a[0]), "r"(a[1]), "r"(a[2]), "r"(a[3]), "r"(b[0]), "r"(b[1]));
}
// swizzled byte offset within an 8KB tile: row r (0..127), byte col bc (0..63, 16B-aligned)
__device__ __forceinline__ uint32_t swz(int r, int bc) {
    return (uint32_t)(r * 64 + ((((bc) >> 4) ^ ((r >> 1) & 3)) << 4));
}

// ---------------------------------------------------------------------------
// Kernel A: BN + SENet + bilinear -> h (bf16 hi/lo split)
// ---------------------------------------------------------------------------
__global__ __launch_bounds__(256) void feat_kernel(
    const float* __restrict__ emb,  const float* __restrict__ bn_w,
    const float* __restrict__ bn_b, const float* __restrict__ bn_m,
    const float* __restrict__ bn_v, const float* __restrict__ se_w1,
    const float* __restrict__ se_w2,const float* __restrict__ w_bl,
    __nv_bfloat16* __restrict__ h_hi, __nv_bfloat16* __restrict__ h_lo)
{
    __shared__ float sV[FE], sT[FE], sZ[F], sH[RDIM], sA[F], sW[E*E];
    __shared__ unsigned char s_pi[P], s_pj[P];

    const int tid = threadIdx.x;
    const int b   = blockIdx.x;

    if (tid == 0) {
        int p = 0;
        for (int i = 0; i < F; i++)
            for (int j = i + 1; j < F; j++) { s_pi[p] = (unsigned char)i; s_pj[p] = (unsigned char)j; p++; }
    }
    if (tid < E*E) sW[tid] = w_bl[tid];

    for (int idx = tid; idx < FE; idx += 256) {
        float x   = emb[(size_t)b * FE + idx];
        float inv = rsqrtf(bn_v[idx] + 1e-5f);
        sV[idx]   = (x - bn_m[idx]) * inv * bn_w[idx] + bn_b[idx];
    }
    __syncthreads();

    if (tid < F) {
        float s = 0.f;
        #pragma unroll
        for (int e = 0; e < E; e++) s += sV[tid * E + e];
        sZ[tid] = s * (1.f / E);
    }
    __syncthreads();

    if (tid < RDIM) {
        float s = 0.f;
        #pragma unroll
        for (int f = 0; f < F; f++) s += sZ[f] * se_w1[tid * F + f];
        sH[tid] = fmaxf(s, 0.f);
    }
    __syncthreads();

    if (tid < F) {
        float s = 0.f;
        #pragma unroll
        for (int r = 0; r < RDIM; r++) s += sH[r] * se_w2[tid * RDIM + r];
        sA[tid] = fmaxf(s, 0.f);
    }

    for (int idx = tid; idx < FE; idx += 256) {
        int f = idx >> 3, d = idx & 7;
        float s = 0.f;
        #pragma unroll
        for (int e = 0; e < E; e++) s += sV[f * E + e] * sW[d * E + e];
        sT[idx] = s;
    }
    __syncthreads();

    __nv_bfloat16* ohi = h_hi + (size_t)b * K1;
    __nv_bfloat16* olo = h_lo + (size_t)b * K1;
    for (int idx = tid; idx < K1; idx += 256) {
        int q = (idx < P * E) ? idx : (idx - P * E);
        int p = q >> 3, d = q & 7;
        int i = s_pi[p], j = s_pj[p];
        float v = sT[i * E + d] * sV[j * E + d];
        if (idx < P * E) v *= sA[i] * sA[j];
        __nv_bfloat16 hh = __float2bfloat16(v);
        ohi[idx] = hh;
        olo[idx] = __float2bfloat16(v - __bfloat162float(hh));
    }
}

// ---------------------------------------------------------------------------
// Weight split fp32 -> bf16 hi/lo
// ---------------------------------------------------------------------------
__global__ __launch_bounds__(256) void split_kernel(
    const float* __restrict__ src, __nv_bfloat16* __restrict__ hi,
    __nv_bfloat16* __restrict__ lo, size_t n)
{
    for (size_t i = (size_t)blockIdx.x * blockDim.x + threadIdx.x; i < n;
         i += (size_t)gridDim.x * blockDim.x) {
        float v = src[i];
        __nv_bfloat16 h = __float2bfloat16(v);
        hi[i] = h;
        lo[i] = __float2bfloat16(v - __bfloat162float(h));
    }
}

// ---------------------------------------------------------------------------
// GEMM1 stream-K phase 1: 296 persistent CTAs, equal kt-unit ranges.
// Single-barrier multistage mainloop (loads issued right after barrier).
// ---------------------------------------------------------------------------
__global__ void __launch_bounds__(256, 2) gemm1_sk(
    const __nv_bfloat16* __restrict__ Ahi, const __nv_bfloat16* __restrict__ Alo,
    const __nv_bfloat16* __restrict__ Bhi, const __nv_bfloat16* __restrict__ Blo,
    const float* __restrict__ bias,
    __nv_bfloat16* __restrict__ Ohi, __nv_bfloat16* __restrict__ Olo,
    float* __restrict__ p0, float* __restrict__ p1)
{
    extern __shared__ char smem[];
    const uint32_t sb  = smem_u32(smem);
    const int tid  = threadIdx.x;
    const int warp = tid >> 5, lane = tid & 31;
    const int wm   = warp & 3;
    const int wn   = warp >> 2;

    // per-thread load coords
    const int r0 = tid >> 2, c0 = tid & 3;
    const uint32_t s_off0 = swz(r0, c0 * 16);
    const uint32_t s_off1 = swz(r0 + 64, c0 * 16);
    const size_t rowK  = (size_t)K1 * 2;
    const size_t g_off0 = (size_t)r0 * rowK + c0 * 16;
    const size_t g_off1 = (size_t)(r0 + 64) * rowK + c0 * 16;

    // ldmatrix lane coords (tile-local)
    const int a_row = wm * 32 + (lane & 15);
    const int a_col = (lane >> 4) * 8;
    const int b_row = wn * 64 + ((lane >> 4) << 3) + (lane & 7);
    const int b_col = ((lane >> 3) & 1) * 8;

    size_t beg = (size_t)blockIdx.x       * U1 / NCTA1;
    size_t end = (size_t)(blockIdx.x + 1) * U1 / NCTA1;

    bool first_seg = true;
    while (beg < end) {
        const int t  = (int)(beg / NKT1);
        const int k0 = (int)(beg % NKT1);
        int L = NKT1 - k0;
        if ((size_t)L > end - beg) L = (int)(end - beg);
        const int bm = t >> 3, bn = t & 7;

        const char* pAh = (const char*)(Ahi + (size_t)bm * BM * K1);
        const char* pAl = (const char*)(Alo + (size_t)bm * BM * K1);
        const char* pBh = (const char*)(Bhi + (size_t)bn * BN * K1);
        const char* pBl = (const char*)(Blo + (size_t)bn * BN * K1);

        float acc[2][8][4];
        #pragma unroll
        for (int i = 0; i < 2; i++)
            #pragma unroll
            for (int j = 0; j < 8; j++)
                #pragma unroll
                for (int r = 0; r < 4; r++) acc[i][j][r] = 0.f;

        auto load_stage = [&](int s, int kt) {
            const uint32_t base = sb + s * STAGE_B;
            const size_t koff = (size_t)kt * (BK * 2);
            cp16(base + s_off0,              pAh + g_off0 + koff);
            cp16(base + s_off1,              pAh + g_off1 + koff);
            cp16(base + TILE_B + s_off0,     pAl + g_off0 + koff);
            cp16(base + TILE_B + s_off1,     pAl + g_off1 + koff);
            cp16(base + 2 * TILE_B + s_off0, pBh + g_off0 + koff);
            cp16(base + 2 * TILE_B + s_off1, pBh + g_off1 + koff);
            cp16(base + 3 * TILE_B + s_off0, pBl + g_off0 + koff);
            cp16(base + 3 * TILE_B + s_off1, pBl + g_off1 + koff);
        };

        // barrier between segments: last ldsm of prev segment vs new writes
        if (!first_seg) __syncthreads();
        first_seg = false;

        load_stage(0, k0);
        asm volatile("cp.async.commit_group;" ::: "memory");
        if (L > 1) load_stage(1, k0 + 1);
        asm volatile("cp.async.commit_group;" ::: "memory");

        for (int i = 0; i < L; i++) {
            const int s = i % NSTAGE;
            asm volatile("cp.async.wait_group 1;" ::: "memory");
            __syncthreads();

            // issue next-stage loads FIRST (stage (i+2)%3 was last read at i-1,
            // which the barrier above proves complete)
            if (i + 2 < L) load_stage((i + 2) % NSTAGE, k0 + i + 2);
            asm volatile("cp.async.commit_group;" ::: "memory");

            const uint32_t base   = sb + s * STAGE_B;
            const uint32_t baseAh = base;
            const uint32_t baseAl = base + TILE_B;
            const uint32_t baseBh = base + 2 * TILE_B;
            const uint32_t baseBl = base + 3 * TILE_B;

            #pragma unroll
            for (int ks = 0; ks < 2; ks++) {
                const int k16 = ks * 16;
                uint32_t ah[2][4], al[2][4];
                #pragma unroll
                for (int mt = 0; mt < 2; mt++) {
                    uint32_t off = swz(a_row + mt * 16, (k16 + a_col) * 2);
                    ldsm_x4(ah[mt], baseAh + off);
                    ldsm_x4(al[mt], baseAl + off);
                }
                #pragma unroll
                for (int half = 0; half < 2; half++) {
                    uint32_t bh[4][2], bl[4][2];
                    #pragma unroll
                    for (int np = 0; np < 2; np++) {
                        uint32_t off = swz(b_row + (half * 2 + np) * 16, (k16 + b_col) * 2);
                        uint32_t rh[4], rl[4];
                        ldsm_x4(rh, baseBh + off);
                        ldsm_x4(rl, baseBl + off);
                        bh[np*2][0]   = rh[0]; bh[np*2][1]   = rh[1];
                        bh[np*2+1][0] = rh[2]; bh[np*2+1][1] = rh[3];
                        bl[np*2][0]   = rl[0]; bl[np*2][1]   = rl[1];
                        bl[np*2+1][0] = rl[2]; bl[np*2+1][1] = rl[3];
                    }
                    #pragma unroll
                    for (int mt = 0; mt < 2; mt++)
                        #pragma unroll
                        for (int nt = 0; nt < 4; nt++) {
                            float* a4 = acc[mt][half * 4 + nt];
                            mma_bf16(a4, ah[mt], bh[nt]);
                            mma_bf16(a4, ah[mt], bl[nt]);
                            mma_bf16(a4, al[mt], bh[nt]);
                        }
                }
            }
        }
        asm volatile("cp.async.wait_group 0;" ::: "memory");

        // ---- epilogue for this segment ----
        const bool full = (k0 == 0) && (L == NKT1);
        const int ml0 = wm * 32 + (lane >> 2);
        const int nl0 = wn * 64 + (lane & 3) * 2;
        if (full) {
            #pragma unroll
            for (int mt = 0; mt < 2; mt++)
                #pragma unroll
                for (int half = 0; half < 2; half++) {
                    const int m = bm * BM + ml0 + mt * 16 + half * 8;
                    #pragma unroll
                    for (int nt = 0; nt < 8; nt++) {
                        const int n = bn * BN + nl0 + nt * 8;
                        float v0 = fmaxf(acc[mt][nt][half*2+0] + __ldg(&bias[n]),   0.f);
                        float v1 = fmaxf(acc[mt][nt][half*2+1] + __ldg(&bias[n+1]), 0.f);
                        __nv_bfloat16 h0 = __float2bfloat16(v0);
                        __nv_bfloat16 h1 = __float2bfloat16(v1);
                        __nv_bfloat162 hv; hv.x = h0; hv.y = h1;
                        __nv_bfloat162 lv;
                        lv.x = __float2bfloat16(v0 - __bfloat162float(h0));
                        lv.y = __float2bfloat16(v1 - __bfloat162float(h1));
                        *(__nv_bfloat162*)(Ohi + (size_t)m * N1 + n) = hv;
                        *(__nv_bfloat162*)(Olo + (size_t)m * N1 + n) = lv;
                    }
                }
        } else {
            float* pp = ((k0 == 0) ? p0 : p1) + (size_t)t * (BM * BN);
            #pragma unroll
            for (int mt = 0; mt < 2; mt++)
                #pragma unroll
                for (int half = 0; half < 2; half++) {
                    const int ml = ml0 + mt * 16 + half * 8;
                    #pragma unroll
                    for (int nt = 0; nt < 8; nt++) {
                        const int nl = nl0 + nt * 8;
                        float2 fv;
                        fv.x = acc[mt][nt][half*2+0];
                        fv.y = acc[mt][nt][half*2+1];
                        *(float2*)(pp + ml * BN + nl) = fv;
                    }
                }
        }
        beg += L;
    }
}

// ---------------------------------------------------------------------------
// GEMM1 stream-K phase 2: combine partials for split tiles (deterministic,
// split-set recomputed arithmetically — no flags).
// ---------------------------------------------------------------------------
__global__ __launch_bounds__(256) void gemm1_fix(
    const float* __restrict__ p0, const float* __restrict__ p1,
    const float* __restrict__ bias,
    __nv_bfloat16* __restrict__ Ohi, __nv_bfloat16* __restrict__ Olo)
{
    const int t = blockIdx.x;
    const unsigned long long lo = (unsigned long long)t * NKT1;
    // smallest CTA boundary strictly greater than lo
    unsigned long long c = ((lo + 1) * NCTA1 + U1 - 1) / U1;
    if (c < 1 || c > NCTA1 - 1) return;
    unsigned long long bnd = c * U1 / NCTA1;
    if (bnd >= lo + NKT1) return;   // no interior boundary -> tile was whole

    const int bm = t >> 3, bn = t & 7;
    const float* a = p0 + (size_t)t * (BM * BN);
    const float* b = p1 + (size_t)t * (BM * BN);

    #pragma unroll 4
    for (int j = 0; j < (BM * BN) / 256; j++) {
        const int idx = threadIdx.x + j * 256;
        const int ml = idx >> 7, nl = idx & 127;
        const int n = bn * BN + nl;
        float v = fmaxf(a[idx] + b[idx] + bias[n], 0.f);
        __nv_bfloat16 h = __float2bfloat16(v);
        const size_t o = (size_t)(bm * BM + ml) * N1 + n;
        Ohi[o] = h;
        Olo[o] = __float2bfloat16(v - __bfloat162float(h));
    }
}

// ---------------------------------------------------------------------------
// bf16x3 GEMM (NT) — classic tiled version (GEMM2), single-barrier mainloop.
// Writes fp32.
// ---------------------------------------------------------------------------
__global__ void __launch_bounds__(256, 2) gemm_bf16x3(
    const __nv_bfloat16* __restrict__ Ahi, const __nv_bfloat16* __restrict__ Alo,
    const __nv_bfloat16* __restrict__ Bhi, const __nv_bfloat16* __restrict__ Blo,
    const float* __restrict__ bias,
    float* __restrict__ Of,
    int Nfull, int K)
{
    extern __shared__ char smem[];
    const uint32_t sb  = smem_u32(smem);
    const int tid  = threadIdx.x;
    const int warp = tid >> 5, lane = tid & 31;
    const int wm   = warp & 3;
    const int wn   = warp >> 2;
    const int bn   = blockIdx.x, bm = blockIdx.y;
    const int nkt  = K / BK;

    const char* pAh = (const char*)(Ahi + (size_t)bm * BM * K);
    const char* pAl = (const char*)(Alo + (size_t)bm * BM * K);
    const char* pBh = (const char*)(Bhi + (size_t)bn * BN * K);
    const char* pBl = (const char*)(Blo + (size_t)bn * BN * K);
    const size_t rowK = (size_t)K * 2;

    const int r0 = tid >> 2, c0 = tid & 3;
    const uint32_t s_off0 = swz(r0, c0 * 16);
    const uint32_t s_off1 = swz(r0 + 64, c0 * 16);
    const size_t  g_off0 = (size_t)r0 * rowK + c0 * 16;
    const size_t  g_off1 = (size_t)(r0 + 64) * rowK + c0 * 16;

    auto load_stage = [&](int s, int kt) {
        const uint32_t base = sb + s * STAGE_B;
        const size_t koff = (size_t)kt * (BK * 2);
        cp16(base + s_off0,              pAh + g_off0 + koff);
        cp16(base + s_off1,              pAh + g_off1 + koff);
        cp16(base + TILE_B + s_off0,     pAl + g_off0 + koff);
        cp16(base + TILE_B + s_off1,     pAl + g_off1 + koff);
        cp16(base + 2 * TILE_B + s_off0, pBh + g_off0 + koff);
        cp16(base + 2 * TILE_B + s_off1, pBh + g_off1 + koff);
        cp16(base + 3 * TILE_B + s_off0, pBl + g_off0 + koff);
        cp16(base + 3 * TILE_B + s_off1, pBl + g_off1 + koff);
    };

    float acc[2][8][4];
    #pragma unroll
    for (int i = 0; i < 2; i++)
        #pragma unroll
        for (int j = 0; j < 8; j++)
            #pragma unroll
            for (int r = 0; r < 4; r++) acc[i][j][r] = 0.f;

    load_stage(0, 0);
    asm volatile("cp.async.commit_group;" ::: "memory");
    if (nkt > 1) load_stage(1, 1);
    asm volatile("cp.async.commit_group;" ::: "memory");

    const int a_row = wm * 32 + (lane & 15);
    const int a_col = (lane >> 4) * 8;
    const int b_row = wn * 64 + ((lane >> 4) << 3) + (lane & 7);
    const int b_col = ((lane >> 3) & 1) * 8;

    for (int kt = 0; kt < nkt; kt++) {
        const int s = kt % NSTAGE;
        asm volatile("cp.async.wait_group 1;" ::: "memory");
        __syncthreads();

        if (kt + 2 < nkt) load_stage((kt + 2) % NSTAGE, kt + 2);
        asm volatile("cp.async.commit_group;" ::: "memory");

        const uint32_t base   = sb + s * STAGE_B;
        const uint32_t baseAh = base;
        const uint32_t baseAl = base + TILE_B;
        const uint32_t baseBh = base + 2 * TILE_B;
        const uint32_t baseBl = base + 3 * TILE_B;

        #pragma unroll
        for (int ks = 0; ks < 2; ks++) {
            const int k0 = ks * 16;
            uint32_t ah[2][4], al[2][4];
            #pragma unroll
            for (int mt = 0; mt < 2; mt++) {
                uint32_t off = swz(a_row + mt * 16, (k0 + a_col) * 2);
                ldsm_x4(ah[mt], baseAh + off);
                ldsm_x4(al[mt], baseAl + off);
            }
            #pragma unroll
            for (int half = 0; half < 2; half++) {
                uint32_t bh[4][2], bl[4][2];
                #pragma unroll
                for (int np = 0; np < 2; np++) {
                    uint32_t off = swz(b_row + (half * 2 + np) * 16, (k0 + b_col) * 2);
                    uint32_t rh[4], rl[4];
                    ldsm_x4(rh, baseBh + off);
                    ldsm_x4(rl, baseBl + off);
                    bh[np*2][0]   = rh[0]; bh[np*2][1]   = rh[1];
                    bh[np*2+1][0] = rh[2]; bh[np*2+1][1] = rh[3];
                    bl[np*2][0]   = rl[0]; bl[np*2][1]   = rl[1];
                    bl[np*2+1][0] = rl[2]; bl[np*2+1][1] = rl[3];
                }
                #pragma unroll
                for (int mt = 0; mt < 2; mt++)
                    #pragma unroll
                    for (int nt = 0; nt < 4; nt++) {
                        float* a4 = acc[mt][half * 4 + nt];
                        mma_bf16(a4, ah[mt], bh[nt]);
                        mma_bf16(a4, ah[mt], bl[nt]);
                        mma_bf16(a4, al[mt], bh[nt]);
                    }
            }
        }
    }

    const int m_base = bm * BM + wm * 32 + (lane >> 2);
    const int n_base = bn * BN + wn * 64 + (lane & 3) * 2;
    #pragma unroll
    for (int mt = 0; mt < 2; mt++) {
        #pragma unroll
        for (int half = 0; half < 2; half++) {
            const int m = m_base + mt * 16 + half * 8;
            #pragma unroll
            for (int nt = 0; nt < 8; nt++) {
                const int n = n_base + nt * 8;
                float2 fv;
                fv.x = fmaxf(acc[mt][nt][half*2+0] + __ldg(&bias[n]),   0.f);
                fv.y = fmaxf(acc[mt][nt][half*2+1] + __ldg(&bias[n+1]), 0.f);
                *(float2*)(Of + (size_t)m * Nfull + n) = fv;
            }
        }
    }
}

// ---------------------------------------------------------------------------
// Final: out[b] = sigmoid( y2[b,:] . w3 + b3 )
// ---------------------------------------------------------------------------
__global__ __launch_bounds__(256) void final_kernel(
    const float* __restrict__ y2, const float* __restrict__ w3,
    const float* __restrict__ b3, float* __restrict__ out)
{
    __shared__ float sw[N2];
    const int tid = threadIdx.x;
    for (int i = tid; i < N2; i += 256) sw[i] = w3[i];
    __syncthreads();

    const int warp = tid >> 5, lane = tid & 31;
    const int row  = blockIdx.x * 8 + warp;
    const float* yr = y2 + (size_t)row * N2;

    float s = 0.f;
    #pragma unroll 4
    for (int k = lane; k < N2; k += 32) s = fmaf(yr[k], sw[k], s);
    #pragma unroll
    for (int o = 16; o; o >>= 1) s += __shfl_xor_sync(0xffffffffu, s, o);
    if (lane == 0) out[row] = 1.f / (1.f + expf(-(s + b3[0])));
}

// ---------------------------------------------------------------------------
extern "C" void kernel_launch(void* const* d_in, const int* in_sizes, int n_in,
                              void* d_out, int out_size)
{
    const float* emb   = (const float*)d_in[0];
    const float* bn_w  = (const float*)d_in[1];
    const float* bn_b  = (const float*)d_in[2];
    const float* bn_m  = (const float*)d_in[3];
    const float* bn_v  = (const float*)d_in[4];
    const float* se_w1 = (const float*)d_in[5];
    const float* se_w2 = (const float*)d_in[6];
    const float* w_bl  = (const float*)d_in[7];
    const float* d_w1  = (const float*)d_in[8];
    const float* d_b1  = (const float*)d_in[9];
    const float* d_w2  = (const float*)d_in[10];
    const float* d_b2  = (const float*)d_in[11];
    const float* d_w3  = (const float*)d_in[12];
    const float* d_b3  = (const float*)d_in[13];
    float* out = (float*)d_out;

    __nv_bfloat16 *h_hi, *h_lo, *w1_hi, *w1_lo, *y1_hi, *y1_lo, *w2_hi, *w2_lo;
    float *y2, *p0, *p1;
    cudaGetSymbolAddress((void**)&h_hi,  g_h_hi);
    cudaGetSymbolAddress((void**)&h_lo,  g_h_lo);
    cudaGetSymbolAddress((void**)&w1_hi, g_w1_hi);
    cudaGetSymbolAddress((void**)&w1_lo, g_w1_lo);
    cudaGetSymbolAddress((void**)&y1_hi, g_y1_hi);
    cudaGetSymbolAddress((void**)&y1_lo, g_y1_lo);
    cudaGetSymbolAddress((void**)&w2_hi, g_w2_hi);
    cudaGetSymbolAddress((void**)&w2_lo, g_w2_lo);
    cudaGetSymbolAddress((void**)&y2,    g_y2);
    cudaGetSymbolAddress((void**)&p0,    g_p0);
    cudaGetSymbolAddress((void**)&p1,    g_p1);

    cudaFuncSetAttribute(gemm1_sk,    cudaFuncAttributeMaxDynamicSharedMemorySize, GEMM_SMEM);
    cudaFuncSetAttribute(gemm_bf16x3, cudaFuncAttributeMaxDynamicSharedMemorySize, GEMM_SMEM);

    // 1) feature construction (bf16 hi/lo)
    feat_kernel<<<B_SZ, 256>>>(emb, bn_w, bn_b, bn_m, bn_v, se_w1, se_w2, w_bl, h_hi, h_lo);

    // 2) weight splits
    split_kernel<<<4096, 256>>>(d_w1, w1_hi, w1_lo, (size_t)N1 * K1);
    split_kernel<<<1024, 256>>>(d_w2, w2_hi, w2_lo, (size_t)N2 * N1);

    // 3) GEMM1 stream-K: [8192,12480] x [1024,12480]^T + relu -> y1 (bf16 split)
    gemm1_sk<<<NCTA1, 256, GEMM_SMEM>>>(h_hi, h_lo, w1_hi, w1_lo, d_b1,
                                        y1_hi, y1_lo, p0, p1);
    gemm1_fix<<<NT1, 256>>>(p0, p1, d_b1, y1_hi, y1_lo);

    // 4) GEMM2: [8192,1024] x [512,1024]^T + relu -> y2 (fp32)
    dim3 g2(N2 / BN, B_SZ / BM);
    gemm_bf16x3<<<g2, 256, GEMM_SMEM>>>(y1_hi, y1_lo, w2_hi, w2_lo, d_b2, y2, N2, N1);

    // 5) GEMV + sigmoid
    final_kernel<<<B_SZ / 8, 256>>>(y2, d_w3, d_b3, out);
}

// round 12
// speedup vs baseline: 1.0549x; 1.0361x over previous
#include <cuda_runtime.h>
#include <cuda_bf16.h>
#include <stdint.h>
#include <math.h>

#define B_SZ 8192
#define F    40
#define E    8
#define FE   320
#define RDIM 5
#define P    780
#define K1   12480
#define N1   1024
#define N2   512

// ---- GEMM tiling ----
#define BM 128
#define BN 128
#define BK 32
#define TILE_B 8192                      // 128 rows x 64B (swizzled, no padding)
#define STAGE_B (4 * TILE_B)             // Ah, Al, Bh, Bl = 32KB
#define NSTAGE 3
#define GEMM_SMEM (NSTAGE * STAGE_B)     // 98304 -> 2 CTAs/SM

// ---- stream-K for GEMM1 ----
#define NKT1  (K1 / BK)                  // 390 kt per tile
#define NTM1  (B_SZ / BM)                // 64
#define NTN1  (N1 / BN)                  // 8
#define NT1   (NTM1 * NTN1)              // 512 tiles
#define NCTA1 296                        // 148 SMs x 2 CTAs
#define U1    ((size_t)NT1 * NKT1)       // 199680 work units

// -------------------- device scratch --------------------
__device__ __nv_bfloat16 g_h_hi [(size_t)B_SZ * K1];
__device__ __nv_bfloat16 g_h_lo [(size_t)B_SZ * K1];
__device__ __nv_bfloat16 g_w1_hi[(size_t)N1 * K1];
__device__ __nv_bfloat16 g_w1_lo[(size_t)N1 * K1];
__device__ __nv_bfloat16 g_y1_hi[(size_t)B_SZ * N1];
__device__ __nv_bfloat16 g_y1_lo[(size_t)B_SZ * N1];
__device__ __nv_bfloat16 g_w2_hi[(size_t)N2 * N1];
__device__ __nv_bfloat16 g_w2_lo[(size_t)N2 * N1];
__device__ float         g_y2  [(size_t)B_SZ * N2];
__device__ float         g_p0  [(size_t)NT1 * BM * BN];   // stream-K partial (k-head)
__device__ float         g_p1  [(size_t)NT1 * BM * BN];   // stream-K partial (k-tail)

// -------------------- helpers --------------------
__device__ __forceinline__ uint32_t smem_u32(const void* p) {
    uint32_t a;
    asm("{ .reg .u64 t; cvta.to.shared.u64 t, %1; cvt.u32.u64 %0, t; }" : "=r"(a) : "l"(p));
    return a;
}
__device__ __forceinline__ void cp16(uint32_t dst, const void* src) {
    asm volatile("cp.async.cg.shared.global [%0], [%1], 16;" :: "r"(dst), "l"(src));
}
__device__ __forceinline__ void ldsm_x4(uint32_t* r, uint32_t addr) {
    asm volatile("ldmatrix.sync.aligned.m8n8.x4.shared.b16 {%0,%1,%2,%3}, [%4];"
                 : "=r"(r[0]), "=r"(r[1]), "=r"(r[2]), "=r"(r[3]) : "r"(addr));
}
__device__ __forceinline__ void mma_bf16(float* c, const uint32_t* a, const uint32_t* b) {
    asm volatile(
        "mma.sync.aligned.m16n8k16.row.col.f32.bf16.bf16.f32 "
        "{%0,%1,%2,%3}, {%4,%5,%6,%7}, {%8,%9}, {%0,%1,%2,%3};"
        : "+f"(c[0]), "+f"(c[1]), "+f"(c[2]), "+f"(c[3])
        : "r"(a[0]), "r"(a[1]), "r"(a[2]), "r"(a[3]), "r"(b[0]), "r"(b[1]));
}
// swizzled byte offset within an 8KB tile: row r (0..127), byte col bc (0..63, 16B-aligned)
__device__ __forceinline__ uint32_t swz(int r, int bc) {
    return (uint32_t)(r * 64 + ((((bc) >> 4) ^ ((r >> 1) & 3)) << 4));
}
__device__ __forceinline__ uint32_t pack_hi(float a, float b, uint32_t& lo) {
    __nv_bfloat16 h0 = __float2bfloat16(a);
    __nv_bfloat16 h1 = __float2bfloat16(b);
    __nv_bfloat162 hp; hp.x = h0; hp.y = h1;
    __nv_bfloat162 lp;
    lp.x = __float2bfloat16(a - __bfloat162float(h0));
    lp.y = __float2bfloat16(b - __bfloat162float(h1));
    lo = *(uint32_t*)&lp;
    return *(uint32_t*)&hp;
}

// ---------------------------------------------------------------------------
// Kernel A: BN + SENet + bilinear -> h (bf16 hi/lo split), vectorized stores.
// One thread handles one pair (8 elems) -> 16B stores.
// ---------------------------------------------------------------------------
__global__ __launch_bounds__(256) void feat_kernel(
    const float* __restrict__ emb,  const float* __restrict__ bn_w,
    const float* __restrict__ bn_b, const float* __restrict__ bn_m,
    const float* __restrict__ bn_v, const float* __restrict__ se_w1,
    const float* __restrict__ se_w2,const float* __restrict__ w_bl,
    __nv_bfloat16* __restrict__ h_hi, __nv_bfloat16* __restrict__ h_lo)
{
    __shared__ float sV[FE], sT[FE], sZ[F], sH[RDIM], sA[F], sW[E*E];
    __shared__ unsigned char s_pi[P], s_pj[P];

    const int tid = threadIdx.x;
    const int b   = blockIdx.x;

    if (tid == 0) {
        int p = 0;
        for (int i = 0; i < F; i++)
            for (int j = i + 1; j < F; j++) { s_pi[p] = (unsigned char)i; s_pj[p] = (unsigned char)j; p++; }
    }
    if (tid < E*E) sW[tid] = w_bl[tid];

    for (int idx = tid; idx < FE; idx += 256) {
        float x   = emb[(size_t)b * FE + idx];
        float inv = rsqrtf(bn_v[idx] + 1e-5f);
        sV[idx]   = (x - bn_m[idx]) * inv * bn_w[idx] + bn_b[idx];
    }
    __syncthreads();

    if (tid < F) {
        float s = 0.f;
        #pragma unroll
        for (int e = 0; e < E; e++) s += sV[tid * E + e];
        sZ[tid] = s * (1.f / E);
    }
    __syncthreads();

    if (tid < RDIM) {
        float s = 0.f;
        #pragma unroll
        for (int f = 0; f < F; f++) s += sZ[f] * se_w1[tid * F + f];
        sH[tid] = fmaxf(s, 0.f);
    }
    __syncthreads();

    if (tid < F) {
        float s = 0.f;
        #pragma unroll
        for (int r = 0; r < RDIM; r++) s += sH[r] * se_w2[tid * RDIM + r];
        sA[tid] = fmaxf(s, 0.f);
    }

    for (int idx = tid; idx < FE; idx += 256) {
        int f = idx >> 3, d = idx & 7;
        float s = 0.f;
        #pragma unroll
        for (int e = 0; e < E; e++) s += sV[f * E + e] * sW[d * E + e];
        sT[idx] = s;
    }
    __syncthreads();

    __nv_bfloat16* ohi = h_hi + (size_t)b * K1;
    __nv_bfloat16* olo = h_lo + (size_t)b * K1;
    for (int g = tid; g < 2 * P; g += 256) {
        const int p = (g < P) ? g : (g - P);
        const int i = s_pi[p], j = s_pj[p];
        const float sc = (g < P) ? (sA[i] * sA[j]) : 1.f;
        const float4 ta = *(const float4*)&sT[i * E];
        const float4 tb = *(const float4*)&sT[i * E + 4];
        const float4 va = *(const float4*)&sV[j * E];
        const float4 vb = *(const float4*)&sV[j * E + 4];
        float v0 = (ta.x * va.x) * sc, v1 = (ta.y * va.y) * sc;
        float v2 = (ta.z * va.z) * sc, v3 = (ta.w * va.w) * sc;
        float v4 = (tb.x * vb.x) * sc, v5 = (tb.y * vb.y) * sc;
        float v6 = (tb.z * vb.z) * sc, v7 = (tb.w * vb.w) * sc;
        uint4 hv, lv;
        hv.x = pack_hi(v0, v1, lv.x);
        hv.y = pack_hi(v2, v3, lv.y);
        hv.z = pack_hi(v4, v5, lv.z);
        hv.w = pack_hi(v6, v7, lv.w);
        *(uint4*)(ohi + (size_t)g * 8) = hv;
        *(uint4*)(olo + (size_t)g * 8) = lv;
    }
}

// ---------------------------------------------------------------------------
// Weight split fp32 -> bf16 hi/lo, vectorized (n must be divisible by 4)
// ---------------------------------------------------------------------------
__global__ __launch_bounds__(256) void split_kernel(
    const float* __restrict__ src, __nv_bfloat16* __restrict__ hi,
    __nv_bfloat16* __restrict__ lo, size_t n4)
{
    for (size_t i = (size_t)blockIdx.x * blockDim.x + threadIdx.x; i < n4;
         i += (size_t)gridDim.x * blockDim.x) {
        float4 v = ((const float4*)src)[i];
        uint2 hv, lv;
        hv.x = pack_hi(v.x, v.y, lv.x);
        hv.y = pack_hi(v.z, v.w, lv.y);
        *(uint2*)(hi + i * 4) = hv;
        *(uint2*)(lo + i * 4) = lv;
    }
}

// ---------------------------------------------------------------------------
// GEMM1 stream-K phase 1: 296 persistent CTAs, equal kt-unit ranges.
// Single-barrier multistage mainloop; MMAs issued in 3 independent passes.
// ---------------------------------------------------------------------------
__global__ void __launch_bounds__(256, 2) gemm1_sk(
    const __nv_bfloat16* __restrict__ Ahi, const __nv_bfloat16* __restrict__ Alo,
    const __nv_bfloat16* __restrict__ Bhi, const __nv_bfloat16* __restrict__ Blo,
    const float* __restrict__ bias,
    __nv_bfloat16* __restrict__ Ohi, __nv_bfloat16* __restrict__ Olo,
    float* __restrict__ p0, float* __restrict__ p1)
{
    extern __shared__ char smem[];
    const uint32_t sb  = smem_u32(smem);
    const int tid  = threadIdx.x;
    const int warp = tid >> 5, lane = tid & 31;
    const int wm   = warp & 3;
    const int wn   = warp >> 2;

    // per-thread load coords
    const int r0 = tid >> 2, c0 = tid & 3;
    const uint32_t s_off0 = swz(r0, c0 * 16);
    const uint32_t s_off1 = swz(r0 + 64, c0 * 16);
    const size_t rowK  = (size_t)K1 * 2;
    const size_t g_off0 = (size_t)r0 * rowK + c0 * 16;
    const size_t g_off1 = (size_t)(r0 + 64) * rowK + c0 * 16;

    // ldmatrix lane coords (tile-local)
    const int a_row = wm * 32 + (lane & 15);
    const int a_col = (lane >> 4) * 8;
    const int b_row = wn * 64 + ((lane >> 4) << 3) + (lane & 7);
    const int b_col = ((lane >> 3) & 1) * 8;

    size_t beg = (size_t)blockIdx.x       * U1 / NCTA1;
    size_t end = (size_t)(blockIdx.x + 1) * U1 / NCTA1;

    bool first_seg = true;
    while (beg < end) {
        const int t  = (int)(beg / NKT1);
        const int k0 = (int)(beg % NKT1);
        int L = NKT1 - k0;
        if ((size_t)L > end - beg) L = (int)(end - beg);
        const int bm = t >> 3, bn = t & 7;

        const char* pAh = (const char*)(Ahi + (size_t)bm * BM * K1);
        const char* pAl = (const char*)(Alo + (size_t)bm * BM * K1);
        const char* pBh = (const char*)(Bhi + (size_t)bn * BN * K1);
        const char* pBl = (const char*)(Blo + (size_t)bn * BN * K1);

        float acc[2][8][4];
        #pragma unroll
        for (int i = 0; i < 2; i++)
            #pragma unroll
            for (int j = 0; j < 8; j++)
                #pragma unroll
                for (int r = 0; r < 4; r++) acc[i][j][r] = 0.f;

        auto load_stage = [&](int s, int kt) {
            const uint32_t base = sb + s * STAGE_B;
            const size_t koff = (size_t)kt * (BK * 2);
            cp16(base + s_off0,              pAh + g_off0 + koff);
            cp16(base + s_off1,              pAh + g_off1 + koff);
            cp16(base + TILE_B + s_off0,     pAl + g_off0 + koff);
            cp16(base + TILE_B + s_off1,     pAl + g_off1 + koff);
            cp16(base + 2 * TILE_B + s_off0, pBh + g_off0 + koff);
            cp16(base + 2 * TILE_B + s_off1, pBh + g_off1 + koff);
            cp16(base + 3 * TILE_B + s_off0, pBl + g_off0 + koff);
            cp16(base + 3 * TILE_B + s_off1, pBl + g_off1 + koff);
        };

        // barrier between segments: last ldsm of prev segment vs new writes
        if (!first_seg) __syncthreads();
        first_seg = false;

        load_stage(0, k0);
        asm volatile("cp.async.commit_group;" ::: "memory");
        if (L > 1) load_stage(1, k0 + 1);
        asm volatile("cp.async.commit_group;" ::: "memory");

        for (int i = 0; i < L; i++) {
            const int s = i % NSTAGE;
            asm volatile("cp.async.wait_group 1;" ::: "memory");
            __syncthreads();

            // issue next-stage loads FIRST (stage (i+2)%3 was last read at i-1,
            // which the barrier above proves complete)
            if (i + 2 < L) load_stage((i + 2) % NSTAGE, k0 + i + 2);
            asm volatile("cp.async.commit_group;" ::: "memory");

            const uint32_t base   = sb + s * STAGE_B;
            const uint32_t baseAh = base;
            const uint32_t baseAl = base + TILE_B;
            const uint32_t baseBh = base + 2 * TILE_B;
            const uint32_t baseBl = base + 3 * TILE_B;

            #pragma unroll
            for (int ks = 0; ks < 2; ks++) {
                const int k16 = ks * 16;
                uint32_t ah[2][4], al[2][4];
                #pragma unroll
                for (int mt = 0; mt < 2; mt++) {
                    uint32_t off = swz(a_row + mt * 16, (k16 + a_col) * 2);
                    ldsm_x4(ah[mt], baseAh + off);
                    ldsm_x4(al[mt], baseAl + off);
                }
                #pragma unroll
                for (int half = 0; half < 2; half++) {
                    uint32_t bh[4][2], bl[4][2];
                    #pragma unroll
                    for (int np = 0; np < 2; np++) {
                        uint32_t off = swz(b_row + (half * 2 + np) * 16, (k16 + b_col) * 2);
                        uint32_t rh[4], rl[4];
                        ldsm_x4(rh, baseBh + off);
                        ldsm_x4(rl, baseBl + off);
                        bh[np*2][0]   = rh[0]; bh[np*2][1]   = rh[1];
                        bh[np*2+1][0] = rh[2]; bh[np*2+1][1] = rh[3];
                        bl[np*2][0]   = rl[0]; bl[np*2][1]   = rl[1];
                        bl[np*2+1][0] = rl[2]; bl[np*2+1][1] = rl[3];
                    }
                    // 3 passes of 8 independent MMAs each; per-acc order
                    // (hh, hl, lh) preserved -> bitwise identical result
                    #pragma unroll
                    for (int mt = 0; mt < 2; mt++)
                        #pragma unroll
                        for (int nt = 0; nt < 4; nt++)
                            mma_bf16(acc[mt][half * 4 + nt], ah[mt], bh[nt]);
                    #pragma unroll
                    for (int mt = 0; mt < 2; mt++)
                        #pragma unroll
                        for (int nt = 0; nt < 4; nt++)
                            mma_bf16(acc[mt][half * 4 + nt], ah[mt], bl[nt]);
                    #pragma unroll
                    for (int mt = 0; mt < 2; mt++)
                        #pragma unroll
                        for (int nt = 0; nt < 4; nt++)
                            mma_bf16(acc[mt][half * 4 + nt], al[mt], bh[nt]);
                }
            }
        }
        asm volatile("cp.async.wait_group 0;" ::: "memory");

        // ---- epilogue for this segment ----
        const bool full = (k0 == 0) && (L == NKT1);
        const int ml0 = wm * 32 + (lane >> 2);
        const int nl0 = wn * 64 + (lane & 3) * 2;
        if (full) {
            #pragma unroll
            for (int mt = 0; mt < 2; mt++)
                #pragma unroll
                for (int half = 0; half < 2; half++) {
                    const int m = bm * BM + ml0 + mt * 16 + half * 8;
                    #pragma unroll
                    for (int nt = 0; nt < 8; nt++) {
                        const int n = bn * BN + nl0 + nt * 8;
                        float v0 = fmaxf(acc[mt][nt][half*2+0] + __ldg(&bias[n]),   0.f);
                        float v1 = fmaxf(acc[mt][nt][half*2+1] + __ldg(&bias[n+1]), 0.f);
                        uint32_t lw;
                        uint32_t hw = pack_hi(v0, v1, lw);
                        *(uint32_t*)(Ohi + (size_t)m * N1 + n) = hw;
                        *(uint32_t*)(Olo + (size_t)m * N1 + n) = lw;
                    }
                }
        } else {
            float* pp = ((k0 == 0) ? p0 : p1) + (size_t)t * (BM * BN);
            #pragma unroll
            for (int mt = 0; mt < 2; mt++)
                #pragma unroll
                for (int half = 0; half < 2; half++) {
                    const int ml = ml0 + mt * 16 + half * 8;
                    #pragma unroll
                    for (int nt = 0; nt < 8; nt++) {
                        const int nl = nl0 + nt * 8;
                        float2 fv;
                        fv.x = acc[mt][nt][half*2+0];
                        fv.y = acc[mt][nt][half*2+1];
                        *(float2*)(pp + ml * BN + nl) = fv;
                    }
                }
        }
        beg += L;
    }
}

// ---------------------------------------------------------------------------
// GEMM1 stream-K phase 2: combine partials for split tiles (deterministic,
// split-set recomputed arithmetically — no flags).
// ---------------------------------------------------------------------------
__global__ __launch_bounds__(256) void gemm1_fix(
    const float* __restrict__ p0, const float* __restrict__ p1,
    const float* __restrict__ bias,
    __nv_bfloat16* __restrict__ Ohi, __nv_bfloat16* __restrict__ Olo)
{
    const int t = blockIdx.x;
    const unsigned long long lo = (unsigned long long)t * NKT1;
    // smallest CTA boundary strictly greater than lo
    unsigned long long c = ((lo + 1) * NCTA1 + U1 - 1) / U1;
    if (c < 1 || c > NCTA1 - 1) return;
    unsigned long long bnd = c * U1 / NCTA1;
    if (bnd >= lo + NKT1) return;   // no interior boundary -> tile was whole

    const int bm = t >> 3, bn = t & 7;
    const float* a = p0 + (size_t)t * (BM * BN);
    const float* b = p1 + (size_t)t * (BM * BN);

    #pragma unroll 4
    for (int j = 0; j < (BM * BN) / 256; j++) {
        const int idx = threadIdx.x + j * 256;
        const int ml = idx >> 7, nl = idx & 127;
        const int n = bn * BN + nl;
        float v = fmaxf(a[idx] + b[idx] + bias[n], 0.f);
        __nv_bfloat16 h = __float2bfloat16(v);
        const size_t o = (size_t)(bm * BM + ml) * N1 + n;
        Ohi[o] = h;
        Olo[o] = __float2bfloat16(v - __bfloat162float(h));
    }
}

// ---------------------------------------------------------------------------
// bf16x3 GEMM (NT) — classic tiled version (GEMM2), single-barrier mainloop.
// Writes fp32.
// ---------------------------------------------------------------------------
__global__ void __launch_bounds__(256, 2) gemm_bf16x3(
    const __nv_bfloat16* __restrict__ Ahi, const __nv_bfloat16* __restrict__ Alo,
    const __nv_bfloat16* __restrict__ Bhi, const __nv_bfloat16* __restrict__ Blo,
    const float* __restrict__ bias,
    float* __restrict__ Of,
    int Nfull, int K)
{
    extern __shared__ char smem[];
    const uint32_t sb  = smem_u32(smem);
    const int tid  = threadIdx.x;
    const int warp = tid >> 5, lane = tid & 31;
    const int wm   = warp & 3;
    const int wn   = warp >> 2;
    const int bn   = blockIdx.x, bm = blockIdx.y;
    const int nkt  = K / BK;

    const char* pAh = (const char*)(Ahi + (size_t)bm * BM * K);
    const char* pAl = (const char*)(Alo + (size_t)bm * BM * K);
    const char* pBh = (const char*)(Bhi + (size_t)bn * BN * K);
    const char* pBl = (const char*)(Blo + (size_t)bn * BN * K);
    const size_t rowK = (size_t)K * 2;

    const int r0 = tid >> 2, c0 = tid & 3;
    const uint32_t s_off0 = swz(r0, c0 * 16);
    const uint32_t s_off1 = swz(r0 + 64, c0 * 16);
    const size_t  g_off0 = (size_t)r0 * rowK + c0 * 16;
    const size_t  g_off1 = (size_t)(r0 + 64) * rowK + c0 * 16;

    auto load_stage = [&](int s, int kt) {
        const uint32_t base = sb + s * STAGE_B;
        const size_t koff = (size_t)kt * (BK * 2);
        cp16(base + s_off0,              pAh + g_off0 + koff);
        cp16(base + s_off1,              pAh + g_off1 + koff);
        cp16(base + TILE_B + s_off0,     pAl + g_off0 + koff);
        cp16(base + TILE_B + s_off1,     pAl + g_off1 + koff);
        cp16(base + 2 * TILE_B + s_off0, pBh + g_off0 + koff);
        cp16(base + 2 * TILE_B + s_off1, pBh + g_off1 + koff);
        cp16(base + 3 * TILE_B + s_off0, pBl + g_off0 + koff);
        cp16(base + 3 * TILE_B + s_off1, pBl + g_off1 + koff);
    };

    float acc[2][8][4];
    #pragma unroll
    for (int i = 0; i < 2; i++)
        #pragma unroll
        for (int j = 0; j < 8; j++)
            #pragma unroll
            for (int r = 0; r < 4; r++) acc[i][j][r] = 0.f;

    load_stage(0, 0);
    asm volatile("cp.async.commit_group;" ::: "memory");
    if (nkt > 1) load_stage(1, 1);
    asm volatile("cp.async.commit_group;" ::: "memory");

    const int a_row = wm * 32 + (lane & 15);
    const int a_col = (lane >> 4) * 8;
    const int b_row = wn * 64 + ((lane >> 4) << 3) + (lane & 7);
    const int b_col = ((lane >> 3) & 1) * 8;

    for (int kt = 0; kt < nkt; kt++) {
        const int s = kt % NSTAGE;
        asm volatile("cp.async.wait_group 1;" ::: "memory");
        __syncthreads();

        if (kt + 2 < nkt) load_stage((kt + 2) % NSTAGE, kt + 2);
        asm volatile("cp.async.commit_group;" ::: "memory");

        const uint32_t base   = sb + s * STAGE_B;
        const uint32_t baseAh = base;
        const uint32_t baseAl = base + TILE_B;
        const uint32_t baseBh = base + 2 * TILE_B;
        const uint32_t baseBl = base + 3 * TILE_B;

        #pragma unroll
        for (int ks = 0; ks < 2; ks++) {
            const int k0 = ks * 16;
            uint32_t ah[2][4], al[2][4];
            #pragma unroll
            for (int mt = 0; mt < 2; mt++) {
                uint32_t off = swz(a_row + mt * 16, (k0 + a_col) * 2);
                ldsm_x4(ah[mt], baseAh + off);
                ldsm_x4(al[mt], baseAl + off);
            }
            #pragma unroll
            for (int half = 0; half < 2; half++) {
                uint32_t bh[4][2], bl[4][2];
                #pragma unroll
                for (int np = 0; np < 2; np++) {
                    uint32_t off = swz(b_row + (half * 2 + np) * 16, (k0 + b_col) * 2);
                    uint32_t rh[4], rl[4];
                    ldsm_x4(rh, baseBh + off);
                    ldsm_x4(rl, baseBl + off);
                    bh[np*2][0]   = rh[0]; bh[np*2][1]   = rh[1];
                    bh[np*2+1][0] = rh[2]; bh[np*2+1][1] = rh[3];
                    bl[np*2][0]   = rl[0]; bl[np*2][1]   = rl[1];
                    bl[np*2+1][0] = rl[2]; bl[np*2+1][1] = rl[3];
                }
                #pragma unroll
                for (int mt = 0; mt < 2; mt++)
                    #pragma unroll
                    for (int nt = 0; nt < 4; nt++)
                        mma_bf16(acc[mt][half * 4 + nt], ah[mt], bh[nt]);
                #pragma unroll
                for (int mt = 0; mt < 2; mt++)
                    #pragma unroll
                    for (int nt = 0; nt < 4; nt++)
                        mma_bf16(acc[mt][half * 4 + nt], ah[mt], bl[nt]);
                #pragma unroll
                for (int mt = 0; mt < 2; mt++)
                    #pragma unroll
                    for (int nt = 0; nt < 4; nt++)
                        mma_bf16(acc[mt][half * 4 + nt], al[mt], bh[nt]);
            }
        }
    }

    const int m_base = bm * BM + wm * 32 + (lane >> 2);
    const int n_base = bn * BN + wn * 64 + (lane & 3) * 2;
    #pragma unroll
    for (int mt = 0; mt < 2; mt++) {
        #pragma unroll
        for (int half = 0; half < 2; half++) {
            const int m = m_base + mt * 16 + half * 8;
            #pragma unroll
            for (int nt = 0; nt < 8; nt++) {
                const int n = n_base + nt * 8;
                float2 fv;
                fv.x = fmaxf(acc[mt][nt][half*2+0] + __ldg(&bias[n]),   0.f);
                fv.y = fmaxf(acc[mt][nt][half*2+1] + __ldg(&bias[n+1]), 0.f);
                *(float2*)(Of + (size_t)m * Nfull + n) = fv;
            }
        }
    }
}

// ---------------------------------------------------------------------------
// Final: out[b] = sigmoid( y2[b,:] . w3 + b3 )
// ---------------------------------------------------------------------------
__global__ __launch_bounds__(256) void final_kernel(
    const float* __restrict__ y2, const float* __restrict__ w3,
    const float* __restrict__ b3, float* __restrict__ out)
{
    __shared__ float sw[N2];
    const int tid = threadIdx.x;
    for (int i = tid; i < N2; i += 256) sw[i] = w3[i];
    __syncthreads();

    const int warp = tid >> 5, lane = tid & 31;
    const int row  = blockIdx.x * 8 + warp;
    const float* yr = y2 + (size_t)row * N2;

    float s = 0.f;
    #pragma unroll 4
    for (int k = lane; k < N2; k += 32) s = fmaf(yr[k], sw[k], s);
    #pragma unroll
    for (int o = 16; o; o >>= 1) s += __shfl_xor_sync(0xffffffffu, s, o);
    if (lane == 0) out[row] = 1.f / (1.f + expf(-(s + b3[0])));
}

// ---------------------------------------------------------------------------
extern "C" void kernel_launch(void* const* d_in, const int* in_sizes, int n_in,
                              void* d_out, int out_size)
{
    const float* emb   = (const float*)d_in[0];
    const float* bn_w  = (const float*)d_in[1];
    const float* bn_b  = (const float*)d_in[2];
    const float* bn_m  = (const float*)d_in[3];
    const float* bn_v  = (const float*)d_in[4];
    const float* se_w1 = (const float*)d_in[5];
    const float* se_w2 = (const float*)d_in[6];
    const float* w_bl  = (const float*)d_in[7];
    const float* d_w1  = (const float*)d_in[8];
    const float* d_b1  = (const float*)d_in[9];
    const float* d_w2  = (const float*)d_in[10];
    const float* d_b2  = (const float*)d_in[11];
    const float* d_w3  = (const float*)d_in[12];
    const float* d_b3  = (const float*)d_in[13];
    float* out = (float*)d_out;

    __nv_bfloat16 *h_hi, *h_lo, *w1_hi, *w1_lo, *y1_hi, *y1_lo, *w2_hi, *w2_lo;
    float *y2, *p0, *p1;
    cudaGetSymbolAddress((void**)&h_hi,  g_h_hi);
    cudaGetSymbolAddress((void**)&h_lo,  g_h_lo);
    cudaGetSymbolAddress((void**)&w1_hi, g_w1_hi);
    cudaGetSymbolAddress((void**)&w1_lo, g_w1_lo);
    cudaGetSymbolAddress((void**)&y1_hi, g_y1_hi);
    cudaGetSymbolAddress((void**)&y1_lo, g_y1_lo);
    cudaGetSymbolAddress((void**)&w2_hi, g_w2_hi);
    cudaGetSymbolAddress((void**)&w2_lo, g_w2_lo);
    cudaGetSymbolAddress((void**)&y2,    g_y2);
    cudaGetSymbolAddress((void**)&p0,    g_p0);
    cudaGetSymbolAddress((void**)&p1,    g_p1);

    cudaFuncSetAttribute(gemm1_sk,    cudaFuncAttributeMaxDynamicSharedMemorySize, GEMM_SMEM);
    cudaFuncSetAttribute(gemm_bf16x3, cudaFuncAttributeMaxDynamicSharedMemorySize, GEMM_SMEM);

    // 1) feature construction (bf16 hi/lo)
    feat_kernel<<<B_SZ, 256>>>(emb, bn_w, bn_b, bn_m, bn_v, se_w1, se_w2, w_bl, h_hi, h_lo);

    // 2) weight splits (vectorized; sizes divisible by 4)
    split_kernel<<<4096, 256>>>(d_w1, w1_hi, w1_lo, (size_t)N1 * K1 / 4);
    split_kernel<<<512,  256>>>(d_w2, w2_hi, w2_lo, (size_t)N2 * N1 / 4);

    // 3) GEMM1 stream-K: [8192,12480] x [1024,12480]^T + relu -> y1 (bf16 split)
    gemm1_sk<<<NCTA1, 256, GEMM_SMEM>>>(h_hi, h_lo, w1_hi, w1_lo, d_b1,
                                        y1_hi, y1_lo, p0, p1);
    gemm1_fix<<<NT1, 256>>>(p0, p1, d_b1, y1_hi, y1_lo);

    // 4) GEMM2: [8192,1024] x [512,1024]^T + relu -> y2 (fp32)
    dim3 g2(N2 / BN, B_SZ / BM);
    gemm_bf16x3<<<g2, 256, GEMM_SMEM>>>(y1_hi, y1_lo, w2_hi, w2_lo, d_b2, y2, N2, N1);

    // 5) GEMV + sigmoid
    final_kernel<<<B_SZ / 8, 256>>>(y2, d_w3, d_b3, out);
}

// round 13
// speedup vs baseline: 2.4173x; 2.2915x over previous
#include <cuda_runtime.h>
#include <cuda_fp16.h>
#include <stdint.h>
#include <math.h>

#define B_SZ 8192
#define F    40
#define E    8
#define FE   320
#define RDIM 5
#define P    780
#define K1   12480
#define N1   1024
#define N2   512

// ---- GEMM tiling ----
#define BM 128
#define BN 128
#define BK 32
#define TILE_B 8192                      // 128 rows x 64B (swizzled, no padding)
#define STAGE_B (2 * TILE_B)             // A, B = 16KB
#define NSTAGE 4
#define GEMM_SMEM (NSTAGE * STAGE_B)     // 65536 -> 2 CTAs/SM

// ---- stream-K for GEMM1 ----
#define NKT1  (K1 / BK)                  // 390 kt per tile
#define NTM1  (B_SZ / BM)                // 64
#define NTN1  (N1 / BN)                  // 8
#define NT1   (NTM1 * NTN1)              // 512 tiles
#define NCTA1 296                        // 148 SMs x 2 CTAs
#define U1    ((size_t)NT1 * NKT1)       // 199680 work units

// -------------------- device scratch --------------------
__device__ __half g_h [(size_t)B_SZ * K1];
__device__ __half g_w1[(size_t)N1 * K1];
__device__ __half g_y1[(size_t)B_SZ * N1];
__device__ __half g_w2[(size_t)N2 * N1];
__device__ float  g_y2[(size_t)B_SZ * N2];
__device__ float  g_p0[(size_t)NT1 * BM * BN];   // stream-K partial (k-head)
__device__ float  g_p1[(size_t)NT1 * BM * BN];   // stream-K partial (k-tail)

// -------------------- helpers --------------------
__device__ __forceinline__ uint32_t smem_u32(const void* p) {
    uint32_t a;
    asm("{ .reg .u64 t; cvta.to.shared.u64 t, %1; cvt.u32.u64 %0, t; }" : "=r"(a) : "l"(p));
    return a;
}
__device__ __forceinline__ void cp16(uint32_t dst, const void* src) {
    asm volatile("cp.async.cg.shared.global [%0], [%1], 16;" :: "r"(dst), "l"(src));
}
__device__ __forceinline__ void ldsm_x4(uint32_t* r, uint32_t addr) {
    asm volatile("ldmatrix.sync.aligned.m8n8.x4.shared.b16 {%0,%1,%2,%3}, [%4];"
                 : "=r"(r[0]), "=r"(r[1]), "=r"(r[2]), "=r"(r[3]) : "r"(addr));
}
__device__ __forceinline__ void mma_fp16(float* c, const uint32_t* a, const uint32_t* b) {
    asm volatile(
        "mma.sync.aligned.m16n8k16.row.col.f32.f16.f16.f32 "
        "{%0,%1,%2,%3}, {%4,%5,%6,%7}, {%8,%9}, {%0,%1,%2,%3};"
        : "+f"(c[0]), "+f"(c[1]), "+f"(c[2]), "+f"(c[3])
        : "r"(a[0]), "r"(a[1]), "r"(a[2]), "r"(a[3]), "r"(b[0]), "r"(b[1]));
}
// swizzled byte offset within an 8KB tile: row r (0..127), byte col bc (0..63, 16B-aligned)
__device__ __forceinline__ uint32_t swz(int r, int bc) {
    return (uint32_t)(r * 64 + ((((bc) >> 4) ^ ((r >> 1) & 3)) << 4));
}
__device__ __forceinline__ uint32_t pack2h(float a, float b) {
    __half2 h = __floats2half2_rn(a, b);
    return *(uint32_t*)&h;
}

// ---------------------------------------------------------------------------
// Kernel A: BN + SENet + bilinear -> h (fp16), vectorized 16B stores.
// ---------------------------------------------------------------------------
__global__ __launch_bounds__(256) void feat_kernel(
    const float* __restrict__ emb,  const float* __restrict__ bn_w,
    const float* __restrict__ bn_b, const float* __restrict__ bn_m,
    const float* __restrict__ bn_v, const float* __restrict__ se_w1,
    const float* __restrict__ se_w2,const float* __restrict__ w_bl,
    __half* __restrict__ h_out)
{
    __shared__ float sV[FE], sT[FE], sZ[F], sH[RDIM], sA[F], sW[E*E];
    __shared__ unsigned char s_pi[P], s_pj[P];

    const int tid = threadIdx.x;
    const int b   = blockIdx.x;

    if (tid == 0) {
        int p = 0;
        for (int i = 0; i < F; i++)
            for (int j = i + 1; j < F; j++) { s_pi[p] = (unsigned char)i; s_pj[p] = (unsigned char)j; p++; }
    }
    if (tid < E*E) sW[tid] = w_bl[tid];

    for (int idx = tid; idx < FE; idx += 256) {
        float x   = emb[(size_t)b * FE + idx];
        float inv = rsqrtf(bn_v[idx] + 1e-5f);
        sV[idx]   = (x - bn_m[idx]) * inv * bn_w[idx] + bn_b[idx];
    }
    __syncthreads();

    if (tid < F) {
        float s = 0.f;
        #pragma unroll
        for (int e = 0; e < E; e++) s += sV[tid * E + e];
        sZ[tid] = s * (1.f / E);
    }
    __syncthreads();

    if (tid < RDIM) {
        float s = 0.f;
        #pragma unroll
        for (int f = 0; f < F; f++) s += sZ[f] * se_w1[tid * F + f];
        sH[tid] = fmaxf(s, 0.f);
    }
    __syncthreads();

    if (tid < F) {
        float s = 0.f;
        #pragma unroll
        for (int r = 0; r < RDIM; r++) s += sH[r] * se_w2[tid * RDIM + r];
        sA[tid] = fmaxf(s, 0.f);
    }

    for (int idx = tid; idx < FE; idx += 256) {
        int f = idx >> 3, d = idx & 7;
        float s = 0.f;
        #pragma unroll
        for (int e = 0; e < E; e++) s += sV[f * E + e] * sW[d * E + e];
        sT[idx] = s;
    }
    __syncthreads();

    __half* oh = h_out + (size_t)b * K1;
    for (int g = tid; g < 2 * P; g += 256) {
        const int p = (g < P) ? g : (g - P);
        const int i = s_pi[p], j = s_pj[p];
        const float sc = (g < P) ? (sA[i] * sA[j]) : 1.f;
        const float4 ta = *(const float4*)&sT[i * E];
        const float4 tb = *(const float4*)&sT[i * E + 4];
        const float4 va = *(const float4*)&sV[j * E];
        const float4 vb = *(const float4*)&sV[j * E + 4];
        uint4 hv;
        hv.x = pack2h((ta.x * va.x) * sc, (ta.y * va.y) * sc);
        hv.y = pack2h((ta.z * va.z) * sc, (ta.w * va.w) * sc);
        hv.z = pack2h((tb.x * vb.x) * sc, (tb.y * vb.y) * sc);
        hv.w = pack2h((tb.z * vb.z) * sc, (tb.w * vb.w) * sc);
        *(uint4*)(oh + (size_t)g * 8) = hv;
    }
}

// ---------------------------------------------------------------------------
// Weight convert fp32 -> fp16, vectorized (n4 = n/4)
// ---------------------------------------------------------------------------
__global__ __launch_bounds__(256) void split_kernel(
    const float* __restrict__ src, __half* __restrict__ dst, size_t n4)
{
    for (size_t i = (size_t)blockIdx.x * blockDim.x + threadIdx.x; i < n4;
         i += (size_t)gridDim.x * blockDim.x) {
        float4 v = ((const float4*)src)[i];
        uint2 hv;
        hv.x = pack2h(v.x, v.y);
        hv.y = pack2h(v.z, v.w);
        *(uint2*)(dst + i * 4) = hv;
    }
}

// ---------------------------------------------------------------------------
// GEMM1 stream-K phase 1 (fp16 single-pass): 296 persistent CTAs.
// 4-stage cp.async pipeline, single barrier per kt.
// ---------------------------------------------------------------------------
__global__ void __launch_bounds__(256, 2) gemm1_sk(
    const __half* __restrict__ A, const __half* __restrict__ B,
    const float* __restrict__ bias,
    __half* __restrict__ Oh,
    float* __restrict__ p0, float* __restrict__ p1)
{
    extern __shared__ char smem[];
    const uint32_t sb  = smem_u32(smem);
    const int tid  = threadIdx.x;
    const int warp = tid >> 5, lane = tid & 31;
    const int wm   = warp & 3;
    const int wn   = warp >> 2;

    // per-thread load coords (2 x 16B chunks per matrix per stage)
    const int r0 = tid >> 2, c0 = tid & 3;
    const uint32_t s_off0 = swz(r0, c0 * 16);
    const uint32_t s_off1 = swz(r0 + 64, c0 * 16);
    const size_t rowK  = (size_t)K1 * 2;
    const size_t g_off0 = (size_t)r0 * rowK + c0 * 16;
    const size_t g_off1 = (size_t)(r0 + 64) * rowK + c0 * 16;

    // ldmatrix lane coords (tile-local)
    const int a_row = wm * 32 + (lane & 15);
    const int a_col = (lane >> 4) * 8;
    const int b_row = wn * 64 + ((lane >> 4) << 3) + (lane & 7);
    const int b_col = ((lane >> 3) & 1) * 8;

    size_t beg = (size_t)blockIdx.x       * U1 / NCTA1;
    size_t end = (size_t)(blockIdx.x + 1) * U1 / NCTA1;

    bool first_seg = true;
    while (beg < end) {
        const int t  = (int)(beg / NKT1);
        const int k0 = (int)(beg % NKT1);
        int L = NKT1 - k0;
        if ((size_t)L > end - beg) L = (int)(end - beg);
        const int bm = t >> 3, bn = t & 7;

        const char* pA = (const char*)(A + (size_t)bm * BM * K1);
        const char* pB = (const char*)(B + (size_t)bn * BN * K1);

        float acc[2][8][4];
        #pragma unroll
        for (int i = 0; i < 2; i++)
            #pragma unroll
            for (int j = 0; j < 8; j++)
                #pragma unroll
                for (int r = 0; r < 4; r++) acc[i][j][r] = 0.f;

        auto load_stage = [&](int s, int kt) {
            const uint32_t base = sb + s * STAGE_B;
            const size_t koff = (size_t)kt * (BK * 2);
            cp16(base + s_off0,          pA + g_off0 + koff);
            cp16(base + s_off1,          pA + g_off1 + koff);
            cp16(base + TILE_B + s_off0, pB + g_off0 + koff);
            cp16(base + TILE_B + s_off1, pB + g_off1 + koff);
        };

        // barrier between segments: last ldsm of prev segment vs new writes
        if (!first_seg) __syncthreads();
        first_seg = false;

        #pragma unroll
        for (int pf = 0; pf < 3; pf++) {
            if (pf < L) load_stage(pf, k0 + pf);
            asm volatile("cp.async.commit_group;" ::: "memory");
        }

        for (int i = 0; i < L; i++) {
            const int s = i & 3;
            asm volatile("cp.async.wait_group 2;" ::: "memory");
            __syncthreads();

            if (i + 3 < L) load_stage((i + 3) & 3, k0 + i + 3);
            asm volatile("cp.async.commit_group;" ::: "memory");

            const uint32_t baseA = sb + s * STAGE_B;
            const uint32_t baseB = baseA + TILE_B;

            #pragma unroll
            for (int ks = 0; ks < 2; ks++) {
                const int k16 = ks * 16;
                uint32_t af[2][4];
                #pragma unroll
                for (int mt = 0; mt < 2; mt++)
                    ldsm_x4(af[mt], baseA + swz(a_row + mt * 16, (k16 + a_col) * 2));
                uint32_t bf[8][2];
                #pragma unroll
                for (int np = 0; np < 4; np++) {
                    uint32_t r[4];
                    ldsm_x4(r, baseB + swz(b_row + np * 16, (k16 + b_col) * 2));
                    bf[np*2][0]   = r[0]; bf[np*2][1]   = r[1];
                    bf[np*2+1][0] = r[2]; bf[np*2+1][1] = r[3];
                }
                #pragma unroll
                for (int mt = 0; mt < 2; mt++)
                    #pragma unroll
                    for (int nt = 0; nt < 8; nt++)
                        mma_fp16(acc[mt][nt], af[mt], bf[nt]);
            }
        }
        asm volatile("cp.async.wait_group 0;" ::: "memory");

        // ---- epilogue for this segment ----
        const bool full = (k0 == 0) && (L == NKT1);
        const int ml0 = wm * 32 + (lane >> 2);
        const int nl0 = wn * 64 + (lane & 3) * 2;
        if (full) {
            #pragma unroll
            for (int mt = 0; mt < 2; mt++)
                #pragma unroll
                for (int half = 0; half < 2; half++) {
                    const int m = bm * BM + ml0 + mt * 16 + half * 8;
                    #pragma unroll
                    for (int nt = 0; nt < 8; nt++) {
                        const int n = bn * BN + nl0 + nt * 8;
                        float v0 = fmaxf(acc[mt][nt][half*2+0] + __ldg(&bias[n]),   0.f);
                        float v1 = fmaxf(acc[mt][nt][half*2+1] + __ldg(&bias[n+1]), 0.f);
                        *(uint32_t*)(Oh + (size_t)m * N1 + n) = pack2h(v0, v1);
                    }
                }
        } else {
            float* pp = ((k0 == 0) ? p0 : p1) + (size_t)t * (BM * BN);
            #pragma unroll
            for (int mt = 0; mt < 2; mt++)
                #pragma unroll
                for (int half = 0; half < 2; half++) {
                    const int ml = ml0 + mt * 16 + half * 8;
                    #pragma unroll
                    for (int nt = 0; nt < 8; nt++) {
                        const int nl = nl0 + nt * 8;
                        float2 fv;
                        fv.x = acc[mt][nt][half*2+0];
                        fv.y = acc[mt][nt][half*2+1];
                        *(float2*)(pp + ml * BN + nl) = fv;
                    }
                }
        }
        beg += L;
    }
}

// ---------------------------------------------------------------------------
// GEMM1 stream-K phase 2: combine partials for split tiles (deterministic).
// ---------------------------------------------------------------------------
__global__ __launch_bounds__(256) void gemm1_fix(
    const float* __restrict__ p0, const float* __restrict__ p1,
    const float* __restrict__ bias,
    __half* __restrict__ Oh)
{
    const int t = blockIdx.x;
    const unsigned long long lo = (unsigned long long)t * NKT1;
    unsigned long long c = ((lo + 1) * NCTA1 + U1 - 1) / U1;
    if (c < 1 || c > NCTA1 - 1) return;
    unsigned long long bnd = c * U1 / NCTA1;
    if (bnd >= lo + NKT1) return;   // no interior boundary -> tile was whole

    const int bm = t >> 3, bn = t & 7;
    const float* a = p0 + (size_t)t * (BM * BN);
    const float* b = p1 + (size_t)t * (BM * BN);

    #pragma unroll 4
    for (int j = 0; j < (BM * BN) / 256; j++) {
        const int idx = threadIdx.x + j * 256;
        const int ml = idx >> 7, nl = idx & 127;
        const int n = bn * BN + nl;
        float v = fmaxf(a[idx] + b[idx] + bias[n], 0.f);
        Oh[(size_t)(bm * BM + ml) * N1 + n] = __float2half_rn(v);
    }
}

// ---------------------------------------------------------------------------
// GEMM2 (fp16 single-pass, NT), classic tiled, single-barrier, writes fp32.
// ---------------------------------------------------------------------------
__global__ void __launch_bounds__(256, 2) gemm_fp16(
    const __half* __restrict__ A, const __half* __restrict__ B,
    const float* __restrict__ bias,
    float* __restrict__ Of,
    int Nfull, int K)
{
    extern __shared__ char smem[];
    const uint32_t sb  = smem_u32(smem);
    const int tid  = threadIdx.x;
    const int warp = tid >> 5, lane = tid & 31;
    const int wm   = warp & 3;
    const int wn   = warp >> 2;
    const int bn   = blockIdx.x, bm = blockIdx.y;
    const int nkt  = K / BK;

    const char* pA = (const char*)(A + (size_t)bm * BM * K);
    const char* pB = (const char*)(B + (size_t)bn * BN * K);
    const size_t rowK = (size_t)K * 2;

    const int r0 = tid >> 2, c0 = tid & 3;
    const uint32_t s_off0 = swz(r0, c0 * 16);
    const uint32_t s_off1 = swz(r0 + 64, c0 * 16);
    const size_t  g_off0 = (size_t)r0 * rowK + c0 * 16;
    const size_t  g_off1 = (size_t)(r0 + 64) * rowK + c0 * 16;

    auto load_stage = [&](int s, int kt) {
        const uint32_t base = sb + s * STAGE_B;
        const size_t koff = (size_t)kt * (BK * 2);
        cp16(base + s_off0,          pA + g_off0 + koff);
        cp16(base + s_off1,          pA + g_off1 + koff);
        cp16(base + TILE_B + s_off0, pB + g_off0 + koff);
        cp16(base + TILE_B + s_off1, pB + g_off1 + koff);
    };

    float acc[2][8][4];
    #pragma unroll
    for (int i = 0; i < 2; i++)
        #pragma unroll
        for (int j = 0; j < 8; j++)
            #pragma unroll
            for (int r = 0; r < 4; r++) acc[i][j][r] = 0.f;

    #pragma unroll
    for (int pf = 0; pf < 3; pf++) {
        if (pf < nkt) load_stage(pf, pf);
        asm volatile("cp.async.commit_group;" ::: "memory");
    }

    const int a_row = wm * 32 + (lane & 15);
    const int a_col = (lane >> 4) * 8;
    const int b_row = wn * 64 + ((lane >> 4) << 3) + (lane & 7);
    const int b_col = ((lane >> 3) & 1) * 8;

    for (int kt = 0; kt < nkt; kt++) {
        const int s = kt & 3;
        asm volatile("cp.async.wait_group 2;" ::: "memory");
        __syncthreads();

        if (kt + 3 < nkt) load_stage((kt + 3) & 3, kt + 3);
        asm volatile("cp.async.commit_group;" ::: "memory");

        const uint32_t baseA = sb + s * STAGE_B;
        const uint32_t baseB = baseA + TILE_B;

        #pragma unroll
        for (int ks = 0; ks < 2; ks++) {
            const int k16 = ks * 16;
            uint32_t af[2][4];
            #pragma unroll
            for (int mt = 0; mt < 2; mt++)
                ldsm_x4(af[mt], baseA + swz(a_row + mt * 16, (k16 + a_col) * 2));
            uint32_t bf[8][2];
            #pragma unroll
            for (int np = 0; np < 4; np++) {
                uint32_t r[4];
                ldsm_x4(r, baseB + swz(b_row + np * 16, (k16 + b_col) * 2));
                bf[np*2][0]   = r[0]; bf[np*2][1]   = r[1];
                bf[np*2+1][0] = r[2]; bf[np*2+1][1] = r[3];
            }
            #pragma unroll
            for (int mt = 0; mt < 2; mt++)
                #pragma unroll
                for (int nt = 0; nt < 8; nt++)
                    mma_fp16(acc[mt][nt], af[mt], bf[nt]);
        }
    }

    const int m_base = bm * BM + wm * 32 + (lane >> 2);
    const int n_base = bn * BN + wn * 64 + (lane & 3) * 2;
    #pragma unroll
    for (int mt = 0; mt < 2; mt++) {
        #pragma unroll
        for (int half = 0; half < 2; half++) {
            const int m = m_base + mt * 16 + half * 8;
            #pragma unroll
            for (int nt = 0; nt < 8; nt++) {
                const int n = n_base + nt * 8;
                float2 fv;
                fv.x = fmaxf(acc[mt][nt][half*2+0] + __ldg(&bias[n]),   0.f);
                fv.y = fmaxf(acc[mt][nt][half*2+1] + __ldg(&bias[n+1]), 0.f);
                *(float2*)(Of + (size_t)m * Nfull + n) = fv;
            }
        }
    }
}

// ---------------------------------------------------------------------------
// Final: out[b] = sigmoid( y2[b,:] . w3 + b3 )
// ---------------------------------------------------------------------------
__global__ __launch_bounds__(256) void final_kernel(
    const float* __restrict__ y2, const float* __restrict__ w3,
    const float* __restrict__ b3, float* __restrict__ out)
{
    __shared__ float sw[N2];
    const int tid = threadIdx.x;
    for (int i = tid; i < N2; i += 256) sw[i] = w3[i];
    __syncthreads();

    const int warp = tid >> 5, lane = tid & 31;
    const int row  = blockIdx.x * 8 + warp;
    const float* yr = y2 + (size_t)row * N2;

    float s = 0.f;
    #pragma unroll 4
    for (int k = lane; k < N2; k += 32) s = fmaf(yr[k], sw[k], s);
    #pragma unroll
    for (int o = 16; o; o >>= 1) s += __shfl_xor_sync(0xffffffffu, s, o);
    if (lane == 0) out[row] = 1.f / (1.f + expf(-(s + b3[0])));
}

// ---------------------------------------------------------------------------
extern "C" void kernel_launch(void* const* d_in, const int* in_sizes, int n_in,
                              void* d_out, int out_size)
{
    const float* emb   = (const float*)d_in[0];
    const float* bn_w  = (const float*)d_in[1];
    const float* bn_b  = (const float*)d_in[2];
    const float* bn_m  = (const float*)d_in[3];
    const float* bn_v  = (const float*)d_in[4];
    const float* se_w1 = (const float*)d_in[5];
    const float* se_w2 = (const float*)d_in[6];
    const float* w_bl  = (const float*)d_in[7];
    const float* d_w1  = (const float*)d_in[8];
    const float* d_b1  = (const float*)d_in[9];
    const float* d_w2  = (const float*)d_in[10];
    const float* d_b2  = (const float*)d_in[11];
    const float* d_w3  = (const float*)d_in[12];
    const float* d_b3  = (const float*)d_in[13];
    float* out = (float*)d_out;

    __half *h, *w1, *y1, *w2;
    float *y2, *p0, *p1;
    cudaGetSymbolAddress((void**)&h,  g_h);
    cudaGetSymbolAddress((void**)&w1, g_w1);
    cudaGetSymbolAddress((void**)&y1, g_y1);
    cudaGetSymbolAddress((void**)&w2, g_w2);
    cudaGetSymbolAddress((void**)&y2, g_y2);
    cudaGetSymbolAddress((void**)&p0, g_p0);
    cudaGetSymbolAddress((void**)&p1, g_p1);

    cudaFuncSetAttribute(gemm1_sk,  cudaFuncAttributeMaxDynamicSharedMemorySize, GEMM_SMEM);
    cudaFuncSetAttribute(gemm_fp16, cudaFuncAttributeMaxDynamicSharedMemorySize, GEMM_SMEM);

    // 1) feature construction (fp16)
    feat_kernel<<<B_SZ, 256>>>(emb, bn_w, bn_b, bn_m, bn_v, se_w1, se_w2, w_bl, h);

    // 2) weight converts (vectorized; sizes divisible by 4)
    split_kernel<<<4096, 256>>>(d_w1, w1, (size_t)N1 * K1 / 4);
    split_kernel<<<512,  256>>>(d_w2, w2, (size_t)N2 * N1 / 4);

    // 3) GEMM1 stream-K: [8192,12480] x [1024,12480]^T + relu -> y1 (fp16)
    gemm1_sk<<<NCTA1, 256, GEMM_SMEM>>>(h, w1, d_b1, y1, p0, p1);
    gemm1_fix<<<NT1, 256>>>(p0, p1, d_b1, y1);

    // 4) GEMM2: [8192,1024] x [512,1024]^T + relu -> y2 (fp32)
    dim3 g2(N2 / BN, B_SZ / BM);
    gemm_fp16<<<g2, 256, GEMM_SMEM>>>(y1, w2, d_b2, y2, N2, N1);

    // 5) GEMV + sigmoid
    final_kernel<<<B_SZ / 8, 256>>>(y2, d_w3, d_b3, out);
}